// round 9
// baseline (speedup 1.0000x reference)
#include <cuda_runtime.h>
#include <cuda_bf16.h>

#define N_NODES 50000
#define N_EDGES 500000
#define N_GRAPHS 100
#define DD 146
#define NS 148          // padded row stride (float), 592B = 37 x float4
#define BN_EPS 1e-5f

// ---------------- scratch (static device globals; no allocation) ----------------
__device__ __align__(16) float g_h   [N_NODES * NS];
__device__ __align__(16) float g_hW  [N_NODES * NS];
__device__ __align__(16) float g_agg [N_NODES * NS];
__device__ float g_norm_src[N_NODES];
__device__ float g_norm_dst[N_NODES];
__device__ float g_counts[N_GRAPHS];
__device__ __align__(16) float g_hg[N_GRAPHS * DD];
__device__ float g_bnsum[2 * NS];   // [0:NS) col sums, [NS:2NS) col sumsq
__device__ float g_mean[NS];
__device__ float g_rstd[NS];

// ---------------- helpers ----------------
__device__ __forceinline__ void red_add_v4(float4* p, float4 v) {
    asm volatile("red.global.add.v4.f32 [%0], {%1,%2,%3,%4};"
                 :: "l"(p), "f"(v.x), "f"(v.y), "f"(v.z), "f"(v.w) : "memory");
}

// ---------------- init (also zeroes agg: first-layer scatter + replay correctness) --------
__global__ void zero_init_kernel() {
    int idx = blockIdx.x * blockDim.x + threadIdx.x;
    int stride = gridDim.x * blockDim.x;
    const float4 z4 = make_float4(0.f, 0.f, 0.f, 0.f);
    const int n4 = N_NODES * NS / 4;
    float4* agg4 = reinterpret_cast<float4*>(g_agg);
    for (int i = idx; i < n4; i += stride) agg4[i] = z4;
    for (int i = idx; i < N_NODES; i += stride) { g_norm_src[i] = 0.f; g_norm_dst[i] = 0.f; }
    for (int i = idx; i < N_GRAPHS * DD; i += stride) g_hg[i] = 0.f;
    for (int i = idx; i < N_GRAPHS; i += stride) g_counts[i] = 0.f;
    for (int i = idx; i < 2 * NS; i += stride) g_bnsum[i] = 0.f;
}

// ---------------- degree norms + graph counts ----------------
__global__ void deg_kernel(const int* __restrict__ src, const int* __restrict__ dst) {
    int idx = blockIdx.x * blockDim.x + threadIdx.x;
    int stride = gridDim.x * blockDim.x;
    for (int e = idx; e < N_EDGES; e += stride) {
        atomicAdd(&g_norm_src[src[e]], 1.0f);
        atomicAdd(&g_norm_dst[dst[e]], 1.0f);
    }
}

__global__ void deg_finalize_kernel(const int* __restrict__ graph_ids) {
    int idx = blockIdx.x * blockDim.x + threadIdx.x;
    int stride = gridDim.x * blockDim.x;
    for (int i = idx; i < N_NODES; i += stride) {
        g_norm_src[i] = rsqrtf(fmaxf(g_norm_src[i], 1.0f));
        g_norm_dst[i] = rsqrtf(fmaxf(g_norm_dst[i], 1.0f));
        atomicAdd(&g_counts[graph_ids[i]], 1.0f);
    }
}

// ---------------- GEMM: C[M,NS] = diag(scale?) * A[M,146] @ W[146,146] (+bias) ----------------
// R9: BK=60 (3 K-tiles 60/60/26), smem 54.7KB + launch_bounds(256,4) -> 4 blocks/SM.
// 256 threads = 16x16, 4(row) x 10(col) micro-tile, BM=64 rows, all 148 cols.
#define GEMM_BM 64
#define GEMM_BK 60
#define GEMM_SMEM_FLOATS (GEMM_BK * 160 + GEMM_BK * 68)
#define GEMM_SMEM_BYTES  (GEMM_SMEM_FLOATS * 4)

__global__ void __launch_bounds__(256, 4)
gemm_kernel(const float* __restrict__ Aext, int use_gh,
            const float* __restrict__ W, const float* __restrict__ bias,
            int use_scale, int out_hw)
{
    extern __shared__ float smem[];
    float* Ws = smem;                     // [60][160]
    float* At = smem + GEMM_BK * 160;     // [60][68] (transposed A tile)

    const float* A = use_gh ? g_h : Aext;
    const int lda = use_gh ? NS : DD;
    float* C = out_hw ? g_hW : g_h;
    const int tid = threadIdx.x;
    const int row0 = blockIdx.x * GEMM_BM;

    const int tx = tid & 15;
    const int ty = tid >> 4;
    float acc[4][10];
#pragma unroll
    for (int i = 0; i < 4; i++)
#pragma unroll
        for (int j = 0; j < 10; j++) acc[i][j] = 0.f;

    const float4* At4 = reinterpret_cast<const float4*>(At);
    const float2* Ws2 = reinterpret_cast<const float2*>(Ws);

    const int KT[4] = {0, 60, 120, 146};
    for (int t = 0; t < 3; t++) {
        const int k0 = KT[t];
        const int klen = KT[t + 1] - k0;
        // stage W tile (+ zero pad cols 146..159)
        for (int i = tid; i < klen * 146; i += 256) {
            int k = i / 146, n = i - k * 146;
            Ws[k * 160 + n] = W[(k0 + k) * 146 + n];
        }
        for (int i = tid; i < klen * 14; i += 256) {
            int k = i / 14, n = 146 + (i - k * 14);
            Ws[k * 160 + n] = 0.f;
        }
        // stage A tile transposed, apply row scale
        for (int i = tid; i < GEMM_BM * klen; i += 256) {
            int r = i / klen, kk = i - r * klen;
            int row = row0 + r;
            float v = 0.f;
            if (row < N_NODES) {
                v = A[(size_t)row * lda + k0 + kk];
                if (use_scale) v *= g_norm_src[row];
            }
            At[kk * 68 + r] = v;
        }
        __syncthreads();

#pragma unroll 2
        for (int kk = 0; kk < klen; kk++) {
            float4 a4 = At4[kk * 17 + ty];
            float av[4] = {a4.x, a4.y, a4.z, a4.w};
#pragma unroll
            for (int j = 0; j < 5; j++) {
                float2 w = Ws2[kk * 80 + tx * 5 + j];
#pragma unroll
                for (int i = 0; i < 4; i++) {
                    acc[i][2 * j]     += av[i] * w.x;
                    acc[i][2 * j + 1] += av[i] * w.y;
                }
            }
        }
        __syncthreads();
    }

#pragma unroll
    for (int i = 0; i < 4; i++) {
        int row = row0 + ty * 4 + i;
        if (row >= N_NODES) continue;
        float* crow = C + (size_t)row * NS;
#pragma unroll
        for (int jj = 0; jj < 10; jj++) {
            int col = tx * 10 + jj;
            if (col < NS) {
                float v = 0.f;
                if (col < DD) {
                    v = acc[i][jj];
                    if (bias) v += bias[col];
                }
                crow[col] = v;
            }
        }
    }
}

// ---------------- edge scatter: agg[dst] += hW[src], vectorized red.v4 ----------------
__global__ void scatter_kernel(const int* __restrict__ src, const int* __restrict__ dst) {
    const int warp_id = (blockIdx.x * blockDim.x + threadIdx.x) >> 5;
    const int lane = threadIdx.x & 31;
    if (warp_id >= N_EDGES) return;
    const int s = __ldg(&src[warp_id]);
    const int d = __ldg(&dst[warp_id]);
    const float4* srow = reinterpret_cast<const float4*>(g_hW + (size_t)s * NS);
    float4* drow = reinterpret_cast<float4*>(g_agg + (size_t)d * NS);
    float4 v = __ldg(&srow[lane]);
    red_add_v4(drow + lane, v);
    if (lane < 5) {
        float4 v2 = __ldg(&srow[32 + lane]);
        red_add_v4(drow + 32 + lane, v2);
    }
}

// ---------------- finalize 1 (R9: stats only, no write-back) ----------------
// v = (agg*norm_dst + b)*snorm computed on the fly; column sums/sumsq -> g_bnsum.
__global__ void finalize1_kernel(const float* __restrict__ snorm,
                                 const float* __restrict__ bs, int layer)
{
    const int f = threadIdx.x;   // blockDim = 160
    const bool active = (f < DD);
    const float b = active ? __ldg(&bs[layer * DD + f]) : 0.f;
    const int per = (N_NODES + gridDim.x - 1) / gridDim.x;
    const int s = blockIdx.x * per;
    const int e = min(s + per, N_NODES);
    float sum = 0.f, sumsq = 0.f;
#pragma unroll 4
    for (int node = s; node < e; node++) {
        float nd = __ldg(&g_norm_dst[node]);
        float sn = __ldg(&snorm[node]);
        if (active) {
            float v = (g_agg[(size_t)node * NS + f] * nd + b) * sn;
            sum += v;
            sumsq += v * v;
        }
    }
    if (active) {
        atomicAdd(&g_bnsum[f], sum);
        atomicAdd(&g_bnsum[NS + f], sumsq);
    }
}

// ---------------- BN stats (+ self-zero bnsum for next layer) ----------------
__global__ void bn_stats_kernel() {
    const int f = threadIdx.x;   // blockDim = 160
    if (f < DD) {
        const float invN = 1.0f / (float)N_NODES;
        float mean = g_bnsum[f] * invN;
        float var = g_bnsum[NS + f] * invN - mean * mean;
        var = fmaxf(var, 0.f);
        g_mean[f] = mean;
        g_rstd[f] = rsqrtf(var + BN_EPS);
    }
    if (f < NS) { g_bnsum[f] = 0.f; g_bnsum[NS + f] = 0.f; }
}

// ---------------- finalize 2 (R9): h += relu(BN(v)); agg=0; per-graph hg accumulation ----
// Recomputes v from raw agg, zeroes agg in place (replaces zero_agg kernel),
// and accumulates hnew per graph (sorted graph_ids -> run-length + atomic flush),
// replacing the g_hacc array and hg_kernel entirely.
__global__ void finalize2_kernel(const float* __restrict__ gammas,
                                 const float* __restrict__ betas,
                                 const float* __restrict__ snorm,
                                 const float* __restrict__ bs,
                                 const int* __restrict__ graph_ids, int layer)
{
    const int f = threadIdx.x;   // blockDim = 160
    const bool active = (f < DD);
    float mean = 0.f, rstd = 0.f, ga = 0.f, be = 0.f, b = 0.f;
    if (active) {
        mean = g_mean[f];
        rstd = g_rstd[f];
        ga = __ldg(&gammas[layer * DD + f]);
        be = __ldg(&betas[layer * DD + f]);
        b  = __ldg(&bs[layer * DD + f]);
    }
    const int per = (N_NODES + gridDim.x - 1) / gridDim.x;
    const int s = blockIdx.x * per;
    const int e = min(s + per, N_NODES);
    int cur = -1;
    float acc = 0.f;
    for (int node = s; node < e; node++) {
        int g = __ldg(&graph_ids[node]);
        if (g != cur) {
            if (cur >= 0 && active) atomicAdd(&g_hg[cur * DD + f], acc);
            cur = g;
            acc = 0.f;
        }
        if (f < NS) {
            size_t idx = (size_t)node * NS + f;
            float a = g_agg[idx];
            g_agg[idx] = 0.f;              // ready for next layer / next replay
            if (active) {
                float nd = __ldg(&g_norm_dst[node]);
                float sn = __ldg(&snorm[node]);
                float v = (a * nd + b) * sn;
                float bn = (v - mean) * rstd * ga + be;
                float hnew = g_h[idx] + fmaxf(bn, 0.f);
                g_h[idx] = hnew;
                acc += hnew;
            }
        }
    }
    if (cur >= 0 && active) atomicAdd(&g_hg[cur * DD + f], acc);
}

// ---------------- MLP readout: 146 -> 73 -> 36 -> 10, one block per graph ----------------
__global__ void readout_kernel(const float* __restrict__ W_r0, const float* __restrict__ b_r0,
                               const float* __restrict__ W_r1, const float* __restrict__ b_r1,
                               const float* __restrict__ W_r2, const float* __restrict__ b_r2,
                               float* __restrict__ out)
{
    __shared__ float sh[DD + 73 + 36];
    const int g = blockIdx.x;
    const int t = threadIdx.x;
    const float inv = 1.0f / fmaxf(g_counts[g], 1.0f);
    for (int k = t; k < DD; k += blockDim.x) sh[k] = g_hg[g * DD + k] * inv;
    __syncthreads();
    if (t < 73) {
        float a = b_r0[t];
        for (int k = 0; k < DD; k++) a += sh[k] * W_r0[k * 73 + t];
        sh[DD + t] = fmaxf(a, 0.f);
    }
    __syncthreads();
    if (t < 36) {
        float a = b_r1[t];
        for (int k = 0; k < 73; k++) a += sh[DD + k] * W_r1[k * 36 + t];
        sh[DD + 73 + t] = fmaxf(a, 0.f);
    }
    __syncthreads();
    if (t < 10) {
        float a = b_r2[t];
        for (int k = 0; k < 36; k++) a += sh[DD + 73 + k] * W_r2[k * 10 + t];
        out[g * 10 + t] = a;
    }
}

// ---------------- launch ----------------
extern "C" void kernel_launch(void* const* d_in, const int* in_sizes, int n_in,
                              void* d_out, int out_size)
{
    const float* nodes_feat = (const float*)d_in[0];
    const float* snorm      = (const float*)d_in[1];
    const float* W_emb      = (const float*)d_in[2];
    const float* b_emb      = (const float*)d_in[3];
    const float* Ws         = (const float*)d_in[4];
    const float* bs         = (const float*)d_in[5];
    const float* gammas     = (const float*)d_in[6];
    const float* betas      = (const float*)d_in[7];
    const float* W_r0       = (const float*)d_in[8];
    const float* b_r0       = (const float*)d_in[9];
    const float* W_r1       = (const float*)d_in[10];
    const float* b_r1       = (const float*)d_in[11];
    const float* W_r2       = (const float*)d_in[12];
    const float* b_r2       = (const float*)d_in[13];
    const int*   src        = (const int*)d_in[14];
    const int*   dst        = (const int*)d_in[15];
    const int*   gid        = (const int*)d_in[16];
    float* out = (float*)d_out;

    cudaFuncSetAttribute(gemm_kernel, cudaFuncAttributeMaxDynamicSharedMemorySize,
                         GEMM_SMEM_BYTES);

    const int gemm_blocks = (N_NODES + GEMM_BM - 1) / GEMM_BM;        // 782
    const int scatter_blocks = (N_EDGES * 32) / 256;                   // 62500

    zero_init_kernel<<<1024, 256>>>();
    deg_kernel<<<(N_EDGES + 255) / 256, 256>>>(src, dst);
    deg_finalize_kernel<<<(N_NODES + 255) / 256, 256>>>(gid);

    // embedding: h = nodes_feat @ W_emb + b_emb
    gemm_kernel<<<gemm_blocks, 256, GEMM_SMEM_BYTES>>>(nodes_feat, 0, W_emb, b_emb, 0, 0);

    for (int l = 0; l < 4; l++) {
        // hW = (h * norm_src) @ W_l
        gemm_kernel<<<gemm_blocks, 256, GEMM_SMEM_BYTES>>>(nullptr, 1, Ws + l * DD * DD,
                                                           nullptr, 1, 1);
        scatter_kernel<<<scatter_blocks, 256>>>(src, dst);
        finalize1_kernel<<<512, 160>>>(snorm, bs, l);
        bn_stats_kernel<<<1, 160>>>();
        finalize2_kernel<<<512, 160>>>(gammas, betas, snorm, bs, gid, l);
    }

    readout_kernel<<<N_GRAPHS, 128>>>(W_r0, b_r0, W_r1, b_r1, W_r2, b_r2, out);
}

// round 10
// speedup vs baseline: 1.6002x; 1.6002x over previous
#include <cuda_runtime.h>
#include <cuda_bf16.h>

#define N_NODES 50000
#define N_EDGES 500000
#define N_GRAPHS 100
#define DD 146
#define NS 148          // padded row stride (float), 592B = 37 x float4
#define BN_EPS 1e-5f

// ---------------- scratch (static device globals; no allocation) ----------------
__device__ __align__(16) float g_h   [N_NODES * NS];
__device__ __align__(16) float g_hW  [N_NODES * NS];
__device__ __align__(16) float g_agg [N_NODES * NS];
__device__ float g_norm_src[N_NODES];
__device__ float g_norm_dst[N_NODES];
__device__ float g_counts[N_GRAPHS];
__device__ __align__(16) float g_hg[N_GRAPHS * DD];
__device__ float g_bnsum[2 * NS];   // [0:NS) col sums, [NS:2NS) col sumsq
__device__ float g_mean[NS];
__device__ float g_rstd[NS];

// ---------------- helpers ----------------
__device__ __forceinline__ void red_add_v4(float4* p, float4 v) {
    asm volatile("red.global.add.v4.f32 [%0], {%1,%2,%3,%4};"
                 :: "l"(p), "f"(v.x), "f"(v.y), "f"(v.z), "f"(v.w) : "memory");
}

// ---------------- init ----------------
__global__ void zero_init_kernel() {
    int idx = blockIdx.x * blockDim.x + threadIdx.x;
    int stride = gridDim.x * blockDim.x;
    for (int i = idx; i < N_NODES; i += stride) { g_norm_src[i] = 0.f; g_norm_dst[i] = 0.f; }
    for (int i = idx; i < N_GRAPHS * DD; i += stride) g_hg[i] = 0.f;
    for (int i = idx; i < N_GRAPHS; i += stride) g_counts[i] = 0.f;
    for (int i = idx; i < 2 * NS; i += stride) g_bnsum[i] = 0.f;
}

// zero agg right before each scatter: ALSO acts as an L2 prefetch+dirty so the
// 18.5M red.add ops hit L2-resident lines (R9 lesson: without this, GEMM traffic
// evicts agg and atomics RMW against DRAM).
__global__ void zero_agg_kernel() {
    int idx = blockIdx.x * blockDim.x + threadIdx.x;
    int stride = gridDim.x * blockDim.x;
    const float4 z4 = make_float4(0.f, 0.f, 0.f, 0.f);
    const int n4 = N_NODES * NS / 4;
    float4* agg4 = reinterpret_cast<float4*>(g_agg);
    for (int i = idx; i < n4; i += stride) agg4[i] = z4;
}

// ---------------- degree norms + graph counts ----------------
__global__ void deg_kernel(const int* __restrict__ src, const int* __restrict__ dst) {
    int idx = blockIdx.x * blockDim.x + threadIdx.x;
    int stride = gridDim.x * blockDim.x;
    for (int e = idx; e < N_EDGES; e += stride) {
        atomicAdd(&g_norm_src[src[e]], 1.0f);
        atomicAdd(&g_norm_dst[dst[e]], 1.0f);
    }
}

__global__ void deg_finalize_kernel(const int* __restrict__ graph_ids) {
    int idx = blockIdx.x * blockDim.x + threadIdx.x;
    int stride = gridDim.x * blockDim.x;
    for (int i = idx; i < N_NODES; i += stride) {
        g_norm_src[i] = rsqrtf(fmaxf(g_norm_src[i], 1.0f));
        g_norm_dst[i] = rsqrtf(fmaxf(g_norm_dst[i], 1.0f));
        atomicAdd(&g_counts[graph_ids[i]], 1.0f);
    }
}

// ---------------- GEMM: C[M,NS] = diag(scale?) * A[M,146] @ W[146,146] (+bias) ----------------
// BK=60 (3 K-tiles 60/60/26), smem 54.7KB + launch_bounds(256,4) -> 4 blocks/SM (R9, measured).
// 256 threads = 16x16, 4(row) x 10(col) micro-tile, BM=64 rows, all 148 cols.
#define GEMM_BM 64
#define GEMM_BK 60
#define GEMM_SMEM_FLOATS (GEMM_BK * 160 + GEMM_BK * 68)
#define GEMM_SMEM_BYTES  (GEMM_SMEM_FLOATS * 4)

__global__ void __launch_bounds__(256, 4)
gemm_kernel(const float* __restrict__ Aext, int use_gh,
            const float* __restrict__ W, const float* __restrict__ bias,
            int use_scale, int out_hw)
{
    extern __shared__ float smem[];
    float* Ws = smem;                     // [60][160]
    float* At = smem + GEMM_BK * 160;     // [60][68] (transposed A tile)

    const float* A = use_gh ? g_h : Aext;
    const int lda = use_gh ? NS : DD;
    float* C = out_hw ? g_hW : g_h;
    const int tid = threadIdx.x;
    const int row0 = blockIdx.x * GEMM_BM;

    const int tx = tid & 15;
    const int ty = tid >> 4;
    float acc[4][10];
#pragma unroll
    for (int i = 0; i < 4; i++)
#pragma unroll
        for (int j = 0; j < 10; j++) acc[i][j] = 0.f;

    const float4* At4 = reinterpret_cast<const float4*>(At);
    const float2* Ws2 = reinterpret_cast<const float2*>(Ws);

    const int KT[4] = {0, 60, 120, 146};
    for (int t = 0; t < 3; t++) {
        const int k0 = KT[t];
        const int klen = KT[t + 1] - k0;
        // stage W tile (+ zero pad cols 146..159)
        for (int i = tid; i < klen * 146; i += 256) {
            int k = i / 146, n = i - k * 146;
            Ws[k * 160 + n] = W[(k0 + k) * 146 + n];
        }
        for (int i = tid; i < klen * 14; i += 256) {
            int k = i / 14, n = 146 + (i - k * 14);
            Ws[k * 160 + n] = 0.f;
        }
        // stage A tile transposed, apply row scale
        for (int i = tid; i < GEMM_BM * klen; i += 256) {
            int r = i / klen, kk = i - r * klen;
            int row = row0 + r;
            float v = 0.f;
            if (row < N_NODES) {
                v = A[(size_t)row * lda + k0 + kk];
                if (use_scale) v *= g_norm_src[row];
            }
            At[kk * 68 + r] = v;
        }
        __syncthreads();

#pragma unroll 2
        for (int kk = 0; kk < klen; kk++) {
            float4 a4 = At4[kk * 17 + ty];
            float av[4] = {a4.x, a4.y, a4.z, a4.w};
#pragma unroll
            for (int j = 0; j < 5; j++) {
                float2 w = Ws2[kk * 80 + tx * 5 + j];
#pragma unroll
                for (int i = 0; i < 4; i++) {
                    acc[i][2 * j]     += av[i] * w.x;
                    acc[i][2 * j + 1] += av[i] * w.y;
                }
            }
        }
        __syncthreads();
    }

#pragma unroll
    for (int i = 0; i < 4; i++) {
        int row = row0 + ty * 4 + i;
        if (row >= N_NODES) continue;
        float* crow = C + (size_t)row * NS;
#pragma unroll
        for (int jj = 0; jj < 10; jj++) {
            int col = tx * 10 + jj;
            if (col < NS) {
                float v = 0.f;
                if (col < DD) {
                    v = acc[i][jj];
                    if (bias) v += bias[col];
                }
                crow[col] = v;
            }
        }
    }
}

// ---------------- edge scatter: agg[dst] += hW[src], vectorized red.v4 ----------------
__global__ void scatter_kernel(const int* __restrict__ src, const int* __restrict__ dst) {
    const int warp_id = (blockIdx.x * blockDim.x + threadIdx.x) >> 5;
    const int lane = threadIdx.x & 31;
    if (warp_id >= N_EDGES) return;
    const int s = __ldg(&src[warp_id]);
    const int d = __ldg(&dst[warp_id]);
    const float4* srow = reinterpret_cast<const float4*>(g_hW + (size_t)s * NS);
    float4* drow = reinterpret_cast<float4*>(g_agg + (size_t)d * NS);
    float4 v = __ldg(&srow[lane]);
    red_add_v4(drow + lane, v);
    if (lane < 5) {
        float4 v2 = __ldg(&srow[32 + lane]);
        red_add_v4(drow + 32 + lane, v2);
    }
}

// ---------------- finalize 1: agg = (agg*norm_dst + b)*snorm (in place) + BN col sums ----------------
__global__ void finalize1_kernel(const float* __restrict__ snorm,
                                 const float* __restrict__ bs, int layer)
{
    const int f = threadIdx.x;   // blockDim = 160
    const bool active = (f < DD);
    const float b = active ? __ldg(&bs[layer * DD + f]) : 0.f;
    const int per = (N_NODES + gridDim.x - 1) / gridDim.x;
    const int s = blockIdx.x * per;
    const int e = min(s + per, N_NODES);
    float sum = 0.f, sumsq = 0.f;
#pragma unroll 4
    for (int node = s; node < e; node++) {
        float nd = __ldg(&g_norm_dst[node]);
        float sn = __ldg(&snorm[node]);
        if (active) {
            size_t idx = (size_t)node * NS + f;
            float v = (g_agg[idx] * nd + b) * sn;
            g_agg[idx] = v;
            sum += v;
            sumsq += v * v;
        }
    }
    if (active) {
        atomicAdd(&g_bnsum[f], sum);
        atomicAdd(&g_bnsum[NS + f], sumsq);
    }
}

// ---------------- BN stats (+ self-zero bnsum for next layer) ----------------
__global__ void bn_stats_kernel() {
    const int f = threadIdx.x;   // blockDim = 160
    if (f < DD) {
        const float invN = 1.0f / (float)N_NODES;
        float mean = g_bnsum[f] * invN;
        float var = g_bnsum[NS + f] * invN - mean * mean;
        var = fmaxf(var, 0.f);
        g_mean[f] = mean;
        g_rstd[f] = rsqrtf(var + BN_EPS);
    }
    if (f < NS) { g_bnsum[f] = 0.f; g_bnsum[NS + f] = 0.f; }
}

// ---------------- finalize 2: h += relu(BN(agg)); per-graph hg run-length accumulation ----
// (R10: replaces g_hacc + hg_kernel — sorted graph_ids -> register accumulator,
//  atomic flush on graph change. ~160K atomics total vs 60MB/layer hacc traffic.)
__global__ void finalize2_kernel(const float* __restrict__ gammas,
                                 const float* __restrict__ betas,
                                 const int* __restrict__ graph_ids, int layer)
{
    const int f = threadIdx.x;   // blockDim = 160
    const bool active = (f < DD);
    float mean = 0.f, rstd = 0.f, ga = 0.f, be = 0.f;
    if (active) {
        mean = g_mean[f];
        rstd = g_rstd[f];
        ga = __ldg(&gammas[layer * DD + f]);
        be = __ldg(&betas[layer * DD + f]);
    }
    const int per = (N_NODES + gridDim.x - 1) / gridDim.x;
    const int s = blockIdx.x * per;
    const int e = min(s + per, N_NODES);
    int cur = -1;
    float acc = 0.f;
    for (int node = s; node < e; node++) {
        int g = __ldg(&graph_ids[node]);
        if (g != cur) {
            if (cur >= 0 && active) atomicAdd(&g_hg[cur * DD + f], acc);
            cur = g;
            acc = 0.f;
        }
        if (active) {
            size_t idx = (size_t)node * NS + f;
            float bn = (g_agg[idx] - mean) * rstd * ga + be;
            float hnew = g_h[idx] + fmaxf(bn, 0.f);
            g_h[idx] = hnew;
            acc += hnew;
        }
    }
    if (cur >= 0 && active) atomicAdd(&g_hg[cur * DD + f], acc);
}

// ---------------- MLP readout: 146 -> 73 -> 36 -> 10, one block per graph ----------------
__global__ void readout_kernel(const float* __restrict__ W_r0, const float* __restrict__ b_r0,
                               const float* __restrict__ W_r1, const float* __restrict__ b_r1,
                               const float* __restrict__ W_r2, const float* __restrict__ b_r2,
                               float* __restrict__ out)
{
    __shared__ float sh[DD + 73 + 36];
    const int g = blockIdx.x;
    const int t = threadIdx.x;
    const float inv = 1.0f / fmaxf(g_counts[g], 1.0f);
    for (int k = t; k < DD; k += blockDim.x) sh[k] = g_hg[g * DD + k] * inv;
    __syncthreads();
    if (t < 73) {
        float a = b_r0[t];
        for (int k = 0; k < DD; k++) a += sh[k] * W_r0[k * 73 + t];
        sh[DD + t] = fmaxf(a, 0.f);
    }
    __syncthreads();
    if (t < 36) {
        float a = b_r1[t];
        for (int k = 0; k < 73; k++) a += sh[DD + k] * W_r1[k * 36 + t];
        sh[DD + 73 + t] = fmaxf(a, 0.f);
    }
    __syncthreads();
    if (t < 10) {
        float a = b_r2[t];
        for (int k = 0; k < 36; k++) a += sh[DD + 73 + k] * W_r2[k * 10 + t];
        out[g * 10 + t] = a;
    }
}

// ---------------- launch ----------------
extern "C" void kernel_launch(void* const* d_in, const int* in_sizes, int n_in,
                              void* d_out, int out_size)
{
    const float* nodes_feat = (const float*)d_in[0];
    const float* snorm      = (const float*)d_in[1];
    const float* W_emb      = (const float*)d_in[2];
    const float* b_emb      = (const float*)d_in[3];
    const float* Ws         = (const float*)d_in[4];
    const float* bs         = (const float*)d_in[5];
    const float* gammas     = (const float*)d_in[6];
    const float* betas      = (const float*)d_in[7];
    const float* W_r0       = (const float*)d_in[8];
    const float* b_r0       = (const float*)d_in[9];
    const float* W_r1       = (const float*)d_in[10];
    const float* b_r1       = (const float*)d_in[11];
    const float* W_r2       = (const float*)d_in[12];
    const float* b_r2       = (const float*)d_in[13];
    const int*   src        = (const int*)d_in[14];
    const int*   dst        = (const int*)d_in[15];
    const int*   gid        = (const int*)d_in[16];
    float* out = (float*)d_out;

    cudaFuncSetAttribute(gemm_kernel, cudaFuncAttributeMaxDynamicSharedMemorySize,
                         GEMM_SMEM_BYTES);

    const int gemm_blocks = (N_NODES + GEMM_BM - 1) / GEMM_BM;        // 782
    const int scatter_blocks = (N_EDGES * 32) / 256;                   // 62500

    zero_init_kernel<<<256, 256>>>();
    deg_kernel<<<(N_EDGES + 255) / 256, 256>>>(src, dst);
    deg_finalize_kernel<<<(N_NODES + 255) / 256, 256>>>(gid);

    // embedding: h = nodes_feat @ W_emb + b_emb
    gemm_kernel<<<gemm_blocks, 256, GEMM_SMEM_BYTES>>>(nodes_feat, 0, W_emb, b_emb, 0, 0);

    for (int l = 0; l < 4; l++) {
        // hW = (h * norm_src) @ W_l
        gemm_kernel<<<gemm_blocks, 256, GEMM_SMEM_BYTES>>>(nullptr, 1, Ws + l * DD * DD,
                                                           nullptr, 1, 1);
        zero_agg_kernel<<<1024, 256>>>();
        scatter_kernel<<<scatter_blocks, 256>>>(src, dst);
        finalize1_kernel<<<512, 160>>>(snorm, bs, l);
        bn_stats_kernel<<<1, 160>>>();
        finalize2_kernel<<<1024, 160>>>(gammas, betas, gid, l);
    }

    readout_kernel<<<N_GRAPHS, 128>>>(W_r0, b_r0, W_r1, b_r1, W_r2, b_r2, out);
}

// round 11
// speedup vs baseline: 1.6722x; 1.0450x over previous
#include <cuda_runtime.h>
#include <cuda_bf16.h>

#define N_NODES 50000
#define N_EDGES 500000
#define N_GRAPHS 100
#define DD 146
#define NS 148          // padded row stride (float), 592B = 37 x float4
#define BN_EPS 1e-5f

// ---------------- scratch (static device globals; no allocation) ----------------
__device__ __align__(16) float g_h   [N_NODES * NS];
__device__ __align__(16) float g_hW  [N_NODES * NS];
__device__ __align__(16) float g_agg [N_NODES * NS];
__device__ float g_norm_src[N_NODES];
__device__ float g_norm_dst[N_NODES];
__device__ float g_counts[N_GRAPHS];
__device__ __align__(16) float g_hg[N_GRAPHS * DD];
__device__ float g_bnsum[2 * NS];   // [0:NS) col sums, [NS:2NS) col sumsq
__device__ float g_mean[NS];
__device__ float g_rstd[NS];

// ---------------- helpers ----------------
__device__ __forceinline__ void red_add_v4(float4* p, float4 v) {
    asm volatile("red.global.add.v4.f32 [%0], {%1,%2,%3,%4};"
                 :: "l"(p), "f"(v.x), "f"(v.y), "f"(v.z), "f"(v.w) : "memory");
}

// pack a scalar into both lanes of an f32x2 register pair
__device__ __forceinline__ unsigned long long pack2(float x) {
    unsigned long long r;
    unsigned u = __float_as_uint(x);
    asm("mov.b64 %0, {%1, %1};" : "=l"(r) : "r"(u));
    return r;
}
// acc += a * b, lanewise on packed f32x2 (SASS FFMA2)
__device__ __forceinline__ void fma2(unsigned long long& acc,
                                     unsigned long long a, unsigned long long b) {
    asm("fma.rn.f32x2 %0, %1, %2, %0;" : "+l"(acc) : "l"(a), "l"(b));
}

// ---------------- init ----------------
__global__ void zero_init_kernel() {
    int idx = blockIdx.x * blockDim.x + threadIdx.x;
    int stride = gridDim.x * blockDim.x;
    for (int i = idx; i < N_NODES; i += stride) { g_norm_src[i] = 0.f; g_norm_dst[i] = 0.f; }
    for (int i = idx; i < N_GRAPHS * DD; i += stride) g_hg[i] = 0.f;
    for (int i = idx; i < N_GRAPHS; i += stride) g_counts[i] = 0.f;
    for (int i = idx; i < 2 * NS; i += stride) g_bnsum[i] = 0.f;
}

// zero agg right before each scatter: ALSO acts as an L2 prefetch+dirty so the
// 18.5M red.add ops hit L2-resident lines (R9 lesson: without this, GEMM traffic
// evicts agg and atomics RMW against DRAM).
__global__ void zero_agg_kernel() {
    int idx = blockIdx.x * blockDim.x + threadIdx.x;
    int stride = gridDim.x * blockDim.x;
    const float4 z4 = make_float4(0.f, 0.f, 0.f, 0.f);
    const int n4 = N_NODES * NS / 4;
    float4* agg4 = reinterpret_cast<float4*>(g_agg);
    for (int i = idx; i < n4; i += stride) agg4[i] = z4;
}

// ---------------- degree norms + graph counts ----------------
__global__ void deg_kernel(const int* __restrict__ src, const int* __restrict__ dst) {
    int idx = blockIdx.x * blockDim.x + threadIdx.x;
    int stride = gridDim.x * blockDim.x;
    for (int e = idx; e < N_EDGES; e += stride) {
        atomicAdd(&g_norm_src[src[e]], 1.0f);
        atomicAdd(&g_norm_dst[dst[e]], 1.0f);
    }
}

__global__ void deg_finalize_kernel(const int* __restrict__ graph_ids) {
    int idx = blockIdx.x * blockDim.x + threadIdx.x;
    int stride = gridDim.x * blockDim.x;
    for (int i = idx; i < N_NODES; i += stride) {
        g_norm_src[i] = rsqrtf(fmaxf(g_norm_src[i], 1.0f));
        g_norm_dst[i] = rsqrtf(fmaxf(g_norm_dst[i], 1.0f));
        atomicAdd(&g_counts[graph_ids[i]], 1.0f);
    }
}

// ---------------- GEMM: C[M,NS] = diag(scale?) * A[M,146] @ W[146,146] (+bias) ----------------
// R11: templated klen (constant divisions in staging) + packed fma.rn.f32x2 inner
// loop (20 FFMA2 vs 40 FFMA per k-iter). BK=60 (tiles 60/60/26), smem 54.7KB.
#define GEMM_BM 64
#define GEMM_BK 60
#define GEMM_SMEM_FLOATS (GEMM_BK * 160 + GEMM_BK * 68)
#define GEMM_SMEM_BYTES  (GEMM_SMEM_FLOATS * 4)

template<int KLEN>
__device__ __forceinline__ void gemm_do_tile(
    const float* __restrict__ A, int lda, const float* __restrict__ W, int k0,
    int row0, int use_scale, float* Ws, float* At, int tid, int tx, int ty,
    unsigned long long acc2[4][5])
{
    // stage W tile rows [k0, k0+KLEN) (+ zero pad cols 146..159)
    for (int i = tid; i < KLEN * 146; i += 256) {
        int k = i / 146, n = i - k * 146;
        Ws[k * 160 + n] = W[(k0 + k) * 146 + n];
    }
    for (int i = tid; i < KLEN * 14; i += 256) {
        int k = i / 14, n = 146 + (i - k * 14);
        Ws[k * 160 + n] = 0.f;
    }
    // stage A tile transposed (KLEN is compile-time -> cheap division)
    for (int i = tid; i < GEMM_BM * KLEN; i += 256) {
        int r = i / KLEN, kk = i - r * KLEN;
        int row = row0 + r;
        float v = 0.f;
        if (row < N_NODES) {
            v = A[(size_t)row * lda + k0 + kk];
            if (use_scale) v *= g_norm_src[row];
        }
        At[kk * 68 + r] = v;
    }
    __syncthreads();

    const float4* pA = reinterpret_cast<const float4*>(At) + ty;
    const unsigned long long* pW = reinterpret_cast<const unsigned long long*>(Ws) + tx * 5;

#pragma unroll 2
    for (int kk = 0; kk < KLEN; kk++) {
        float4 a4 = pA[kk * 17];
        unsigned long long av0 = pack2(a4.x);
        unsigned long long av1 = pack2(a4.y);
        unsigned long long av2 = pack2(a4.z);
        unsigned long long av3 = pack2(a4.w);
#pragma unroll
        for (int j = 0; j < 5; j++) {
            unsigned long long w = pW[kk * 80 + j];
            fma2(acc2[0][j], av0, w);
            fma2(acc2[1][j], av1, w);
            fma2(acc2[2][j], av2, w);
            fma2(acc2[3][j], av3, w);
        }
    }
    __syncthreads();
}

__global__ void __launch_bounds__(256, 3)
gemm_kernel(const float* __restrict__ Aext, int use_gh,
            const float* __restrict__ W, const float* __restrict__ bias,
            int use_scale, int out_hw)
{
    extern __shared__ float smem[];
    float* Ws = smem;                     // [60][160]
    float* At = smem + GEMM_BK * 160;     // [60][68] (transposed A tile)

    const float* A = use_gh ? g_h : Aext;
    const int lda = use_gh ? NS : DD;
    float* C = out_hw ? g_hW : g_h;
    const int tid = threadIdx.x;
    const int row0 = blockIdx.x * GEMM_BM;
    const int tx = tid & 15;
    const int ty = tid >> 4;

    unsigned long long acc2[4][5];
#pragma unroll
    for (int i = 0; i < 4; i++)
#pragma unroll
        for (int j = 0; j < 5; j++) acc2[i][j] = 0ULL;

    gemm_do_tile<60>(A, lda, W,   0, row0, use_scale, Ws, At, tid, tx, ty, acc2);
    gemm_do_tile<60>(A, lda, W,  60, row0, use_scale, Ws, At, tid, tx, ty, acc2);
    gemm_do_tile<26>(A, lda, W, 120, row0, use_scale, Ws, At, tid, tx, ty, acc2);

#pragma unroll
    for (int i = 0; i < 4; i++) {
        int row = row0 + ty * 4 + i;
        if (row >= N_NODES) continue;
        float* crow = C + (size_t)row * NS;
#pragma unroll
        for (int j = 0; j < 5; j++) {
            uint2 u = *reinterpret_cast<uint2*>(&acc2[i][j]);
            float lo = __uint_as_float(u.x);
            float hi = __uint_as_float(u.y);
            int col = tx * 10 + 2 * j;
            if (col < NS) {
                float v0 = 0.f, v1 = 0.f;
                if (col < DD)     { v0 = lo; if (bias) v0 += bias[col]; }
                if (col + 1 < DD) { v1 = hi; if (bias) v1 += bias[col + 1]; }
                crow[col] = v0;
                if (col + 1 < NS) crow[col + 1] = v1;
            }
        }
    }
}

// ---------------- edge scatter: agg[dst] += hW[src], vectorized red.v4 ----------------
__global__ void scatter_kernel(const int* __restrict__ src, const int* __restrict__ dst) {
    const int warp_id = (blockIdx.x * blockDim.x + threadIdx.x) >> 5;
    const int lane = threadIdx.x & 31;
    if (warp_id >= N_EDGES) return;
    const int s = __ldg(&src[warp_id]);
    const int d = __ldg(&dst[warp_id]);
    const float4* srow = reinterpret_cast<const float4*>(g_hW + (size_t)s * NS);
    float4* drow = reinterpret_cast<float4*>(g_agg + (size_t)d * NS);
    float4 v = __ldg(&srow[lane]);
    red_add_v4(drow + lane, v);
    if (lane < 5) {
        float4 v2 = __ldg(&srow[32 + lane]);
        red_add_v4(drow + 32 + lane, v2);
    }
}

// ---------------- finalize 1: agg = (agg*norm_dst + b)*snorm (in place) + BN col sums ----------------
__global__ void finalize1_kernel(const float* __restrict__ snorm,
                                 const float* __restrict__ bs, int layer)
{
    const int f = threadIdx.x;   // blockDim = 160
    const bool active = (f < DD);
    const float b = active ? __ldg(&bs[layer * DD + f]) : 0.f;
    const int per = (N_NODES + gridDim.x - 1) / gridDim.x;
    const int s = blockIdx.x * per;
    const int e = min(s + per, N_NODES);
    float sum = 0.f, sumsq = 0.f;
#pragma unroll 4
    for (int node = s; node < e; node++) {
        float nd = __ldg(&g_norm_dst[node]);
        float sn = __ldg(&snorm[node]);
        if (active) {
            size_t idx = (size_t)node * NS + f;
            float v = (g_agg[idx] * nd + b) * sn;
            g_agg[idx] = v;
            sum += v;
            sumsq += v * v;
        }
    }
    if (active) {
        atomicAdd(&g_bnsum[f], sum);
        atomicAdd(&g_bnsum[NS + f], sumsq);
    }
}

// ---------------- BN stats (+ self-zero bnsum for next layer) ----------------
__global__ void bn_stats_kernel() {
    const int f = threadIdx.x;   // blockDim = 160
    if (f < DD) {
        const float invN = 1.0f / (float)N_NODES;
        float mean = g_bnsum[f] * invN;
        float var = g_bnsum[NS + f] * invN - mean * mean;
        var = fmaxf(var, 0.f);
        g_mean[f] = mean;
        g_rstd[f] = rsqrtf(var + BN_EPS);
    }
    if (f < NS) { g_bnsum[f] = 0.f; g_bnsum[NS + f] = 0.f; }
}

// ---------------- finalize 2: h += relu(BN(agg)); per-graph hg run-length accumulation ----
__global__ void finalize2_kernel(const float* __restrict__ gammas,
                                 const float* __restrict__ betas,
                                 const int* __restrict__ graph_ids, int layer)
{
    const int f = threadIdx.x;   // blockDim = 160
    const bool active = (f < DD);
    float mean = 0.f, rstd = 0.f, ga = 0.f, be = 0.f;
    if (active) {
        mean = g_mean[f];
        rstd = g_rstd[f];
        ga = __ldg(&gammas[layer * DD + f]);
        be = __ldg(&betas[layer * DD + f]);
    }
    const int per = (N_NODES + gridDim.x - 1) / gridDim.x;
    const int s = blockIdx.x * per;
    const int e = min(s + per, N_NODES);
    int cur = -1;
    float acc = 0.f;
    for (int node = s; node < e; node++) {
        int g = __ldg(&graph_ids[node]);
        if (g != cur) {
            if (cur >= 0 && active) atomicAdd(&g_hg[cur * DD + f], acc);
            cur = g;
            acc = 0.f;
        }
        if (active) {
            size_t idx = (size_t)node * NS + f;
            float bn = (g_agg[idx] - mean) * rstd * ga + be;
            float hnew = g_h[idx] + fmaxf(bn, 0.f);
            g_h[idx] = hnew;
            acc += hnew;
        }
    }
    if (cur >= 0 && active) atomicAdd(&g_hg[cur * DD + f], acc);
}

// ---------------- MLP readout: 146 -> 73 -> 36 -> 10, one block per graph ----------------
__global__ void readout_kernel(const float* __restrict__ W_r0, const float* __restrict__ b_r0,
                               const float* __restrict__ W_r1, const float* __restrict__ b_r1,
                               const float* __restrict__ W_r2, const float* __restrict__ b_r2,
                               float* __restrict__ out)
{
    __shared__ float sh[DD + 73 + 36];
    const int g = blockIdx.x;
    const int t = threadIdx.x;
    const float inv = 1.0f / fmaxf(g_counts[g], 1.0f);
    for (int k = t; k < DD; k += blockDim.x) sh[k] = g_hg[g * DD + k] * inv;
    __syncthreads();
    if (t < 73) {
        float a = b_r0[t];
        for (int k = 0; k < DD; k++) a += sh[k] * W_r0[k * 73 + t];
        sh[DD + t] = fmaxf(a, 0.f);
    }
    __syncthreads();
    if (t < 36) {
        float a = b_r1[t];
        for (int k = 0; k < 73; k++) a += sh[DD + k] * W_r1[k * 36 + t];
        sh[DD + 73 + t] = fmaxf(a, 0.f);
    }
    __syncthreads();
    if (t < 10) {
        float a = b_r2[t];
        for (int k = 0; k < 36; k++) a += sh[DD + 73 + k] * W_r2[k * 10 + t];
        out[g * 10 + t] = a;
    }
}

// ---------------- launch ----------------
extern "C" void kernel_launch(void* const* d_in, const int* in_sizes, int n_in,
                              void* d_out, int out_size)
{
    const float* nodes_feat = (const float*)d_in[0];
    const float* snorm      = (const float*)d_in[1];
    const float* W_emb      = (const float*)d_in[2];
    const float* b_emb      = (const float*)d_in[3];
    const float* Ws         = (const float*)d_in[4];
    const float* bs         = (const float*)d_in[5];
    const float* gammas     = (const float*)d_in[6];
    const float* betas      = (const float*)d_in[7];
    const float* W_r0       = (const float*)d_in[8];
    const float* b_r0       = (const float*)d_in[9];
    const float* W_r1       = (const float*)d_in[10];
    const float* b_r1       = (const float*)d_in[11];
    const float* W_r2       = (const float*)d_in[12];
    const float* b_r2       = (const float*)d_in[13];
    const int*   src        = (const int*)d_in[14];
    const int*   dst        = (const int*)d_in[15];
    const int*   gid        = (const int*)d_in[16];
    float* out = (float*)d_out;

    cudaFuncSetAttribute(gemm_kernel, cudaFuncAttributeMaxDynamicSharedMemorySize,
                         GEMM_SMEM_BYTES);

    const int gemm_blocks = (N_NODES + GEMM_BM - 1) / GEMM_BM;        // 782
    const int scatter_blocks = (N_EDGES * 32) / 256;                   // 62500

    zero_init_kernel<<<256, 256>>>();
    deg_kernel<<<(N_EDGES + 255) / 256, 256>>>(src, dst);
    deg_finalize_kernel<<<(N_NODES + 255) / 256, 256>>>(gid);

    // embedding: h = nodes_feat @ W_emb + b_emb
    gemm_kernel<<<gemm_blocks, 256, GEMM_SMEM_BYTES>>>(nodes_feat, 0, W_emb, b_emb, 0, 0);

    for (int l = 0; l < 4; l++) {
        // hW = (h * norm_src) @ W_l
        gemm_kernel<<<gemm_blocks, 256, GEMM_SMEM_BYTES>>>(nullptr, 1, Ws + l * DD * DD,
                                                           nullptr, 1, 1);
        zero_agg_kernel<<<1024, 256>>>();
        scatter_kernel<<<scatter_blocks, 256>>>(src, dst);
        finalize1_kernel<<<512, 160>>>(snorm, bs, l);
        bn_stats_kernel<<<1, 160>>>();
        finalize2_kernel<<<1024, 160>>>(gammas, betas, gid, l);
    }

    readout_kernel<<<N_GRAPHS, 128>>>(W_r0, b_r0, W_r1, b_r1, W_r2, b_r2, out);
}

// round 13
// speedup vs baseline: 1.7756x; 1.0619x over previous
#include <cuda_runtime.h>
#include <cuda_bf16.h>
#include <cstdint>

#define N_NODES 50000
#define N_EDGES 500000
#define N_GRAPHS 100
#define DD 146
#define NS 148          // padded row stride (float), 592B = 37 x float4
#define BN_EPS 1e-5f

// ---------------- scratch (static device globals; no allocation) ----------------
__device__ __align__(16) float g_h   [N_NODES * NS];
__device__ __align__(16) float g_hW  [N_NODES * NS];
__device__ __align__(16) float g_agg [N_NODES * NS];
__device__ float g_norm_src[N_NODES];
__device__ float g_norm_dst[N_NODES];
__device__ float g_counts[N_GRAPHS];
__device__ __align__(16) float g_hg[N_GRAPHS * DD];
__device__ float g_bnsum[2 * NS];   // [0:NS) col sums, [NS:2NS) col sumsq
__device__ float g_mean[NS];
__device__ float g_rstd[NS];

// ---------------- helpers ----------------
__device__ __forceinline__ void red_add_v4(float4* p, float4 v) {
    asm volatile("red.global.add.v4.f32 [%0], {%1,%2,%3,%4};"
                 :: "l"(p), "f"(v.x), "f"(v.y), "f"(v.z), "f"(v.w) : "memory");
}
__device__ __forceinline__ uint32_t f2tf32(float x) {
    uint32_t r;
    asm("cvt.rna.tf32.f32 %0, %1;" : "=r"(r) : "f"(x));
    return r;
}
// m16n8k8 tf32 MMA (legacy HMMA path, valid on target sm_100)
__device__ __forceinline__ void mma8(float* c, const uint32_t* a, uint32_t b0, uint32_t b1) {
    asm volatile(
        "mma.sync.aligned.m16n8k8.row.col.f32.tf32.tf32.f32 "
        "{%0,%1,%2,%3}, {%4,%5,%6,%7}, {%8,%9}, {%0,%1,%2,%3};"
        : "+f"(c[0]), "+f"(c[1]), "+f"(c[2]), "+f"(c[3])
        : "r"(a[0]), "r"(a[1]), "r"(a[2]), "r"(a[3]), "r"(b0), "r"(b1));
}

// ---------------- init ----------------
__global__ void zero_init_kernel() {
    int idx = blockIdx.x * blockDim.x + threadIdx.x;
    int stride = gridDim.x * blockDim.x;
    for (int i = idx; i < N_NODES; i += stride) { g_norm_src[i] = 0.f; g_norm_dst[i] = 0.f; }
    for (int i = idx; i < N_GRAPHS * DD; i += stride) g_hg[i] = 0.f;
    for (int i = idx; i < N_GRAPHS; i += stride) g_counts[i] = 0.f;
    for (int i = idx; i < 2 * NS; i += stride) g_bnsum[i] = 0.f;
}

// zero agg right before each scatter (L2 prefetch+dirty; R9 lesson)
__global__ void zero_agg_kernel() {
    int idx = blockIdx.x * blockDim.x + threadIdx.x;
    int stride = gridDim.x * blockDim.x;
    const float4 z4 = make_float4(0.f, 0.f, 0.f, 0.f);
    const int n4 = N_NODES * NS / 4;
    float4* agg4 = reinterpret_cast<float4*>(g_agg);
    for (int i = idx; i < n4; i += stride) agg4[i] = z4;
}

// ---------------- degree norms + graph counts ----------------
__global__ void deg_kernel(const int* __restrict__ src, const int* __restrict__ dst) {
    int idx = blockIdx.x * blockDim.x + threadIdx.x;
    int stride = gridDim.x * blockDim.x;
    for (int e = idx; e < N_EDGES; e += stride) {
        atomicAdd(&g_norm_src[src[e]], 1.0f);
        atomicAdd(&g_norm_dst[dst[e]], 1.0f);
    }
}

__global__ void deg_finalize_kernel(const int* __restrict__ graph_ids) {
    int idx = blockIdx.x * blockDim.x + threadIdx.x;
    int stride = gridDim.x * blockDim.x;
    for (int i = idx; i < N_NODES; i += stride) {
        g_norm_src[i] = rsqrtf(fmaxf(g_norm_src[i], 1.0f));
        g_norm_dst[i] = rsqrtf(fmaxf(g_norm_dst[i], 1.0f));
        atomicAdd(&g_counts[graph_ids[i]], 1.0f);
    }
}

// ---------------- mma.sync tf32 GEMM (3-pass split = fp32 accuracy) ----------------
// C[M,NS] = diag(scale?) * A[M,146] @ W[146,146] (+bias)
// Block: 256 thr / 8 warps; tile M=128 (warp owns 16 rows), N=152 (19 n8 tiles),
// K=152 (19 k8 steps). W split (hi/lo tf32) staged in smem [152][WST]; A fragments
// loaded straight from gmem (L2-hot) with one-step prefetch.
// D = Ah*Bh + Ah*Bl + Al*Bh  (|Al*Bl| ~ 2^-22, dropped)
#define TCM 128
#define KPAD 152
#define WST 168   // smem row stride: k*WST+n -> (8k+n)&31 => 32 distinct banks per B-frag load
#define W_SMEM_FLOATS (KPAD * WST)
#define MMA_SMEM_BYTES (2 * W_SMEM_FLOATS * 4)   // 204,288 B

__global__ void __launch_bounds__(256, 1)
mma_gemm_kernel(const float* __restrict__ Aext, int use_gh,
                const float* __restrict__ W, const float* __restrict__ bias,
                int use_scale, int out_hw)
{
    extern __shared__ float smem[];
    float* Whi = smem;
    float* Wlo = smem + W_SMEM_FLOATS;
    const float* A = use_gh ? g_h : Aext;
    const int lda = use_gh ? NS : DD;
    float* C = out_hw ? g_hW : g_h;
    const int tid = threadIdx.x;

    // stage W: hi = tf32(w), lo = tf32(w - hi); zero pads (k or n >= 146)
    for (int i = tid; i < KPAD * 152; i += 256) {
        int k = i / 152, n = i - (i / 152) * 152;
        float w = (k < DD && n < DD) ? __ldg(&W[k * DD + n]) : 0.f;
        float whi = __uint_as_float(f2tf32(w));
        float wlo = __uint_as_float(f2tf32(w - whi));
        Whi[k * WST + n] = whi;
        Wlo[k * WST + n] = wlo;
    }
    __syncthreads();

    const int warp = tid >> 5;
    const int lane = tid & 31;
    const int tg = lane & 3;          // thread-in-group (k / col-pair selector)
    const int gid = lane >> 2;        // group id (row / n selector)
    const int rlo = blockIdx.x * TCM + warp * 16 + gid;
    const int rhi = rlo + 8;
    const bool vlo = rlo < N_NODES, vhi = rhi < N_NODES;
    const float slo = (use_scale && vlo) ? g_norm_src[rlo] : 1.f;
    const float shi = (use_scale && vhi) ? g_norm_src[rhi] : 1.f;
    const float* Aplo = A + (size_t)rlo * lda;
    const float* Aphi = A + (size_t)rhi * lda;

    float acc[19][4];
#pragma unroll
    for (int j = 0; j < 19; j++) {
        acc[j][0] = 0.f; acc[j][1] = 0.f; acc[j][2] = 0.f; acc[j][3] = 0.f;
    }

    // prefetch k-step 0 (cols tg, tg+4 < 146 always)
    float ar0 = vlo ? Aplo[tg] * slo : 0.f;
    float ar1 = vhi ? Aphi[tg] * shi : 0.f;
    float ar2 = vlo ? Aplo[tg + 4] * slo : 0.f;
    float ar3 = vhi ? Aphi[tg + 4] * shi : 0.f;

#pragma unroll 1
    for (int s = 0; s < 19; s++) {
        float a0 = ar0, a1 = ar1, a2 = ar2, a3 = ar3;
        if (s < 18) {
            int c0 = 8 * (s + 1) + tg, c1 = c0 + 4;
            bool g0 = c0 < DD, g1 = c1 < DD;
            ar0 = (vlo && g0) ? Aplo[c0] * slo : 0.f;
            ar1 = (vhi && g0) ? Aphi[c0] * shi : 0.f;
            ar2 = (vlo && g1) ? Aplo[c1] * slo : 0.f;
            ar3 = (vhi && g1) ? Aphi[c1] * shi : 0.f;
        }
        uint32_t ah[4], al[4];
        ah[0] = f2tf32(a0); al[0] = f2tf32(a0 - __uint_as_float(ah[0]));
        ah[1] = f2tf32(a1); al[1] = f2tf32(a1 - __uint_as_float(ah[1]));
        ah[2] = f2tf32(a2); al[2] = f2tf32(a2 - __uint_as_float(ah[2]));
        ah[3] = f2tf32(a3); al[3] = f2tf32(a3 - __uint_as_float(ah[3]));

        const float* wh = Whi + 8 * s * WST;
        const float* wl = Wlo + 8 * s * WST;
#pragma unroll
        for (int j = 0; j < 19; j++) {
            int nn = j * 8 + gid;
            uint32_t bh0 = __float_as_uint(wh[tg * WST + nn]);
            uint32_t bh1 = __float_as_uint(wh[(tg + 4) * WST + nn]);
            uint32_t bl0 = __float_as_uint(wl[tg * WST + nn]);
            uint32_t bl1 = __float_as_uint(wl[(tg + 4) * WST + nn]);
            mma8(acc[j], ah, bh0, bh1);
            mma8(acc[j], ah, bl0, bl1);
            mma8(acc[j], al, bh0, bh1);
        }
    }

    // epilogue: c0/c1 -> row rlo cols (8j+2tg, +1); c2/c3 -> row rhi
#pragma unroll
    for (int j = 0; j < 19; j++) {
        int col = j * 8 + 2 * tg;
        if (col < NS) {   // col even, <=146 -> col+1 <= 147 < NS
            float bx = 0.f, by = 0.f;
            if (bias) {
                if (col < DD)     bx = __ldg(&bias[col]);
                if (col + 1 < DD) by = __ldg(&bias[col + 1]);
            }
            if (vlo) {
                float2 v;
                v.x = (col < DD)     ? acc[j][0] + bx : 0.f;
                v.y = (col + 1 < DD) ? acc[j][1] + by : 0.f;
                *reinterpret_cast<float2*>(C + (size_t)rlo * NS + col) = v;
            }
            if (vhi) {
                float2 v;
                v.x = (col < DD)     ? acc[j][2] + bx : 0.f;
                v.y = (col + 1 < DD) ? acc[j][3] + by : 0.f;
                *reinterpret_cast<float2*>(C + (size_t)rhi * NS + col) = v;
            }
        }
    }
}

// ---------------- edge scatter: agg[dst] += hW[src], vectorized red.v4 ----------------
__global__ void scatter_kernel(const int* __restrict__ src, const int* __restrict__ dst) {
    const int warp_id = (blockIdx.x * blockDim.x + threadIdx.x) >> 5;
    const int lane = threadIdx.x & 31;
    if (warp_id >= N_EDGES) return;
    const int s = __ldg(&src[warp_id]);
    const int d = __ldg(&dst[warp_id]);
    const float4* srow = reinterpret_cast<const float4*>(g_hW + (size_t)s * NS);
    float4* drow = reinterpret_cast<float4*>(g_agg + (size_t)d * NS);
    float4 v = __ldg(&srow[lane]);
    red_add_v4(drow + lane, v);
    if (lane < 5) {
        float4 v2 = __ldg(&srow[32 + lane]);
        red_add_v4(drow + 32 + lane, v2);
    }
}

// ---------------- finalize 1: agg = (agg*norm_dst + b)*snorm (in place) + BN col sums ----------------
__global__ void finalize1_kernel(const float* __restrict__ snorm,
                                 const float* __restrict__ bs, int layer)
{
    const int f = threadIdx.x;   // blockDim = 160
    const bool active = (f < DD);
    const float b = active ? __ldg(&bs[layer * DD + f]) : 0.f;
    const int per = (N_NODES + gridDim.x - 1) / gridDim.x;
    const int s = blockIdx.x * per;
    const int e = min(s + per, N_NODES);
    float sum = 0.f, sumsq = 0.f;
#pragma unroll 4
    for (int node = s; node < e; node++) {
        float nd = __ldg(&g_norm_dst[node]);
        float sn = __ldg(&snorm[node]);
        if (active) {
            size_t idx = (size_t)node * NS + f;
            float v = (g_agg[idx] * nd + b) * sn;
            g_agg[idx] = v;
            sum += v;
            sumsq += v * v;
        }
    }
    if (active) {
        atomicAdd(&g_bnsum[f], sum);
        atomicAdd(&g_bnsum[NS + f], sumsq);
    }
}

// ---------------- BN stats (+ self-zero bnsum for next layer) ----------------
__global__ void bn_stats_kernel() {
    const int f = threadIdx.x;   // blockDim = 160
    if (f < DD) {
        const float invN = 1.0f / (float)N_NODES;
        float mean = g_bnsum[f] * invN;
        float var = g_bnsum[NS + f] * invN - mean * mean;
        var = fmaxf(var, 0.f);
        g_mean[f] = mean;
        g_rstd[f] = rsqrtf(var + BN_EPS);
    }
    if (f < NS) { g_bnsum[f] = 0.f; g_bnsum[NS + f] = 0.f; }
}

// ---------------- finalize 2: h += relu(BN(agg)); per-graph hg run-length accumulation ----
__global__ void finalize2_kernel(const float* __restrict__ gammas,
                                 const float* __restrict__ betas,
                                 const int* __restrict__ graph_ids, int layer)
{
    const int f = threadIdx.x;   // blockDim = 160
    const bool active = (f < DD);
    float mean = 0.f, rstd = 0.f, ga = 0.f, be = 0.f;
    if (active) {
        mean = g_mean[f];
        rstd = g_rstd[f];
        ga = __ldg(&gammas[layer * DD + f]);
        be = __ldg(&betas[layer * DD + f]);
    }
    const int per = (N_NODES + gridDim.x - 1) / gridDim.x;
    const int s = blockIdx.x * per;
    const int e = min(s + per, N_NODES);
    int cur = -1;
    float acc = 0.f;
    for (int node = s; node < e; node++) {
        int g = __ldg(&graph_ids[node]);
        if (g != cur) {
            if (cur >= 0 && active) atomicAdd(&g_hg[cur * DD + f], acc);
            cur = g;
            acc = 0.f;
        }
        if (active) {
            size_t idx = (size_t)node * NS + f;
            float bn = (g_agg[idx] - mean) * rstd * ga + be;
            float hnew = g_h[idx] + fmaxf(bn, 0.f);
            g_h[idx] = hnew;
            acc += hnew;
        }
    }
    if (cur >= 0 && active) atomicAdd(&g_hg[cur * DD + f], acc);
}

// ---------------- MLP readout: 146 -> 73 -> 36 -> 10, one block per graph ----------------
__global__ void readout_kernel(const float* __restrict__ W_r0, const float* __restrict__ b_r0,
                               const float* __restrict__ W_r1, const float* __restrict__ b_r1,
                               const float* __restrict__ W_r2, const float* __restrict__ b_r2,
                               float* __restrict__ out)
{
    __shared__ float sh[DD + 73 + 36];
    const int g = blockIdx.x;
    const int t = threadIdx.x;
    const float inv = 1.0f / fmaxf(g_counts[g], 1.0f);
    for (int k = t; k < DD; k += blockDim.x) sh[k] = g_hg[g * DD + k] * inv;
    __syncthreads();
    if (t < 73) {
        float a = b_r0[t];
        for (int k = 0; k < DD; k++) a += sh[k] * W_r0[k * 73 + t];
        sh[DD + t] = fmaxf(a, 0.f);
    }
    __syncthreads();
    if (t < 36) {
        float a = b_r1[t];
        for (int k = 0; k < 73; k++) a += sh[DD + k] * W_r1[k * 36 + t];
        sh[DD + 73 + t] = fmaxf(a, 0.f);
    }
    __syncthreads();
    if (t < 10) {
        float a = b_r2[t];
        for (int k = 0; k < 36; k++) a += sh[DD + 73 + k] * W_r2[k * 10 + t];
        out[g * 10 + t] = a;
    }
}

// ---------------- launch ----------------
extern "C" void kernel_launch(void* const* d_in, const int* in_sizes, int n_in,
                              void* d_out, int out_size)
{
    const float* nodes_feat = (const float*)d_in[0];
    const float* snorm      = (const float*)d_in[1];
    const float* W_emb      = (const float*)d_in[2];
    const float* b_emb      = (const float*)d_in[3];
    const float* Ws         = (const float*)d_in[4];
    const float* bs         = (const float*)d_in[5];
    const float* gammas     = (const float*)d_in[6];
    const float* betas      = (const float*)d_in[7];
    const float* W_r0       = (const float*)d_in[8];
    const float* b_r0       = (const float*)d_in[9];
    const float* W_r1       = (const float*)d_in[10];
    const float* b_r1       = (const float*)d_in[11];
    const float* W_r2       = (const float*)d_in[12];
    const float* b_r2       = (const float*)d_in[13];
    const int*   src        = (const int*)d_in[14];
    const int*   dst        = (const int*)d_in[15];
    const int*   gid        = (const int*)d_in[16];
    float* out = (float*)d_out;

    cudaFuncSetAttribute(mma_gemm_kernel, cudaFuncAttributeMaxDynamicSharedMemorySize,
                         MMA_SMEM_BYTES);

    const int gemm_blocks = (N_NODES + TCM - 1) / TCM;                 // 391
    const int scatter_blocks = (N_EDGES * 32) / 256;                    // 62500

    zero_init_kernel<<<256, 256>>>();
    deg_kernel<<<(N_EDGES + 255) / 256, 256>>>(src, dst);
    deg_finalize_kernel<<<(N_NODES + 255) / 256, 256>>>(gid);

    // embedding: h = nodes_feat @ W_emb + b_emb
    mma_gemm_kernel<<<gemm_blocks, 256, MMA_SMEM_BYTES>>>(nodes_feat, 0, W_emb, b_emb, 0, 0);

    for (int l = 0; l < 4; l++) {
        // hW = (h * norm_src) @ W_l
        mma_gemm_kernel<<<gemm_blocks, 256, MMA_SMEM_BYTES>>>(nullptr, 1, Ws + l * DD * DD,
                                                              nullptr, 1, 1);
        zero_agg_kernel<<<1024, 256>>>();
        scatter_kernel<<<scatter_blocks, 256>>>(src, dst);
        finalize1_kernel<<<512, 160>>>(snorm, bs, l);
        bn_stats_kernel<<<1, 160>>>();
        finalize2_kernel<<<1024, 160>>>(gammas, betas, gid, l);
    }

    readout_kernel<<<N_GRAPHS, 128>>>(W_r0, b_r0, W_r1, b_r1, W_r2, b_r2, out);
}

// round 14
// speedup vs baseline: 1.9092x; 1.0752x over previous
#include <cuda_runtime.h>
#include <cuda_bf16.h>
#include <cstdint>

#define N_NODES 50000
#define N_EDGES 500000
#define N_GRAPHS 100
#define DD 146
#define NS 148          // padded row stride (float), 592B = 37 x float4
#define BN_EPS 1e-5f

// ---------------- scratch (static device globals; no allocation) ----------------
__device__ __align__(16) float g_h   [N_NODES * NS];
__device__ __align__(16) float g_hW  [N_NODES * NS];
__device__ __align__(16) float g_agg [N_NODES * NS];
__device__ float g_norm_src[N_NODES];
__device__ float g_norm_dst[N_NODES];
__device__ float g_counts[N_GRAPHS];
__device__ __align__(16) float g_hg[N_GRAPHS * DD];
__device__ float g_bnsum[2 * NS];   // [0:NS) col sums, [NS:2NS) col sumsq
__device__ float g_mean[NS];
__device__ float g_rstd[NS];

// ---------------- helpers ----------------
__device__ __forceinline__ void red_add_v4(float4* p, float4 v) {
    asm volatile("red.global.add.v4.f32 [%0], {%1,%2,%3,%4};"
                 :: "l"(p), "f"(v.x), "f"(v.y), "f"(v.z), "f"(v.w) : "memory");
}
__device__ __forceinline__ uint32_t f2tf32(float x) {
    uint32_t r;
    asm("cvt.rna.tf32.f32 %0, %1;" : "=r"(r) : "f"(x));
    return r;
}
// m16n8k8 tf32 MMA (legacy HMMA path, valid on target sm_100)
__device__ __forceinline__ void mma8(float* c, const uint32_t* a, uint32_t b0, uint32_t b1) {
    asm volatile(
        "mma.sync.aligned.m16n8k8.row.col.f32.tf32.tf32.f32 "
        "{%0,%1,%2,%3}, {%4,%5,%6,%7}, {%8,%9}, {%0,%1,%2,%3};"
        : "+f"(c[0]), "+f"(c[1]), "+f"(c[2]), "+f"(c[3])
        : "r"(a[0]), "r"(a[1]), "r"(a[2]), "r"(a[3]), "r"(b0), "r"(b1));
}

// ---------------- init ----------------
__global__ void zero_init_kernel() {
    int idx = blockIdx.x * blockDim.x + threadIdx.x;
    int stride = gridDim.x * blockDim.x;
    for (int i = idx; i < N_NODES; i += stride) { g_norm_src[i] = 0.f; g_norm_dst[i] = 0.f; }
    for (int i = idx; i < N_GRAPHS * DD; i += stride) g_hg[i] = 0.f;
    for (int i = idx; i < N_GRAPHS; i += stride) g_counts[i] = 0.f;
    for (int i = idx; i < 2 * NS; i += stride) g_bnsum[i] = 0.f;
}

// zero agg right before each scatter (L2 prefetch+dirty; R9 lesson)
__global__ void zero_agg_kernel() {
    int idx = blockIdx.x * blockDim.x + threadIdx.x;
    int stride = gridDim.x * blockDim.x;
    const float4 z4 = make_float4(0.f, 0.f, 0.f, 0.f);
    const int n4 = N_NODES * NS / 4;
    float4* agg4 = reinterpret_cast<float4*>(g_agg);
    for (int i = idx; i < n4; i += stride) agg4[i] = z4;
}

// ---------------- degree norms + graph counts ----------------
__global__ void deg_kernel(const int* __restrict__ src, const int* __restrict__ dst) {
    int idx = blockIdx.x * blockDim.x + threadIdx.x;
    int stride = gridDim.x * blockDim.x;
    for (int e = idx; e < N_EDGES; e += stride) {
        atomicAdd(&g_norm_src[src[e]], 1.0f);
        atomicAdd(&g_norm_dst[dst[e]], 1.0f);
    }
}

__global__ void deg_finalize_kernel(const int* __restrict__ graph_ids) {
    int idx = blockIdx.x * blockDim.x + threadIdx.x;
    int stride = gridDim.x * blockDim.x;
    for (int i = idx; i < N_NODES; i += stride) {
        g_norm_src[i] = rsqrtf(fmaxf(g_norm_src[i], 1.0f));
        g_norm_dst[i] = rsqrtf(fmaxf(g_norm_dst[i], 1.0f));
        atomicAdd(&g_counts[graph_ids[i]], 1.0f);
    }
}

// ---------------- mma.sync tf32 GEMM (3-pass split = fp32 accuracy) ----------------
// C[M,NS] = diag(scale?) * A[M,146] @ W[146,146] (+bias)
// R14: N-split across blockIdx.y — each block does M=128 x N=80 (10 n8-tiles),
// staging only its W column slice (hi/lo) in smem [152][88] -> 107KB, regs<=128
// -> 2 blocks/SM (vs 1 in R13: occ 12.1%, tensor 25%).
// D = Ah*Bh + Ah*Bl + Al*Bh  (|Al*Bl| ~ 2^-22, dropped)
#define TCM 128
#define TCN 80     // N cols per block
#define NT 10      // n8 tiles per block
#define KPAD 152
#define WST 88     // smem row stride: banks tg*88%32={0,24,16,8} + gid -> 32 distinct
#define W_SMEM_FLOATS (KPAD * WST)
#define MMA_SMEM_BYTES (2 * W_SMEM_FLOATS * 4)   // 107,008 B

__global__ void __launch_bounds__(256, 2)
mma_gemm_kernel(const float* __restrict__ Aext, int use_gh,
                const float* __restrict__ W, const float* __restrict__ bias,
                int use_scale, int out_hw)
{
    extern __shared__ float smem[];
    float* Whi = smem;
    float* Wlo = smem + W_SMEM_FLOATS;
    const float* A = use_gh ? g_h : Aext;
    const int lda = use_gh ? NS : DD;
    float* C = out_hw ? g_hW : g_h;
    const int tid = threadIdx.x;
    const int n0 = blockIdx.y * TCN;

    // stage W column slice [all k][n0..n0+79]: hi = tf32(w), lo = tf32(w - hi)
    for (int i = tid; i < KPAD * TCN; i += 256) {
        int k = i / TCN, n = i - (i / TCN) * TCN;
        int gn = n0 + n;
        float w = (k < DD && gn < DD) ? __ldg(&W[k * DD + gn]) : 0.f;
        float whi = __uint_as_float(f2tf32(w));
        float wlo = __uint_as_float(f2tf32(w - whi));
        Whi[k * WST + n] = whi;
        Wlo[k * WST + n] = wlo;
    }
    __syncthreads();

    const int warp = tid >> 5;
    const int lane = tid & 31;
    const int tg = lane & 3;          // thread-in-group (k / col-pair selector)
    const int gid = lane >> 2;        // group id (row / n selector)
    const int rlo = blockIdx.x * TCM + warp * 16 + gid;
    const int rhi = rlo + 8;
    const bool vlo = rlo < N_NODES, vhi = rhi < N_NODES;
    const float slo = (use_scale && vlo) ? g_norm_src[rlo] : 1.f;
    const float shi = (use_scale && vhi) ? g_norm_src[rhi] : 1.f;
    const float* Aplo = A + (size_t)rlo * lda;
    const float* Aphi = A + (size_t)rhi * lda;

    float acc[NT][4];
#pragma unroll
    for (int j = 0; j < NT; j++) {
        acc[j][0] = 0.f; acc[j][1] = 0.f; acc[j][2] = 0.f; acc[j][3] = 0.f;
    }

    // prefetch k-step 0 (cols tg, tg+4 < 146 always)
    float ar0 = vlo ? Aplo[tg] * slo : 0.f;
    float ar1 = vhi ? Aphi[tg] * shi : 0.f;
    float ar2 = vlo ? Aplo[tg + 4] * slo : 0.f;
    float ar3 = vhi ? Aphi[tg + 4] * shi : 0.f;

#pragma unroll 1
    for (int s = 0; s < 19; s++) {
        float a0 = ar0, a1 = ar1, a2 = ar2, a3 = ar3;
        if (s < 18) {
            int c0 = 8 * (s + 1) + tg, c1 = c0 + 4;
            bool g0 = c0 < DD, g1 = c1 < DD;
            ar0 = (vlo && g0) ? Aplo[c0] * slo : 0.f;
            ar1 = (vhi && g0) ? Aphi[c0] * shi : 0.f;
            ar2 = (vlo && g1) ? Aplo[c1] * slo : 0.f;
            ar3 = (vhi && g1) ? Aphi[c1] * shi : 0.f;
        }
        uint32_t ah[4], al[4];
        ah[0] = f2tf32(a0); al[0] = f2tf32(a0 - __uint_as_float(ah[0]));
        ah[1] = f2tf32(a1); al[1] = f2tf32(a1 - __uint_as_float(ah[1]));
        ah[2] = f2tf32(a2); al[2] = f2tf32(a2 - __uint_as_float(ah[2]));
        ah[3] = f2tf32(a3); al[3] = f2tf32(a3 - __uint_as_float(ah[3]));

        const float* wh = Whi + 8 * s * WST;
        const float* wl = Wlo + 8 * s * WST;
#pragma unroll
        for (int j = 0; j < NT; j++) {
            int nn = j * 8 + gid;   // local col within block slice
            uint32_t bh0 = __float_as_uint(wh[tg * WST + nn]);
            uint32_t bh1 = __float_as_uint(wh[(tg + 4) * WST + nn]);
            uint32_t bl0 = __float_as_uint(wl[tg * WST + nn]);
            uint32_t bl1 = __float_as_uint(wl[(tg + 4) * WST + nn]);
            mma8(acc[j], ah, bh0, bh1);
            mma8(acc[j], ah, bl0, bl1);
            mma8(acc[j], al, bh0, bh1);
        }
    }

    // epilogue: c0/c1 -> row rlo cols (n0+8j+2tg, +1); c2/c3 -> row rhi
#pragma unroll
    for (int j = 0; j < NT; j++) {
        int col = n0 + j * 8 + 2 * tg;
        if (col < NS) {   // col even -> col+1 < NS whenever col < NS
            float bx = 0.f, by = 0.f;
            if (bias) {
                if (col < DD)     bx = __ldg(&bias[col]);
                if (col + 1 < DD) by = __ldg(&bias[col + 1]);
            }
            if (vlo) {
                float2 v;
                v.x = (col < DD)     ? acc[j][0] + bx : 0.f;
                v.y = (col + 1 < DD) ? acc[j][1] + by : 0.f;
                *reinterpret_cast<float2*>(C + (size_t)rlo * NS + col) = v;
            }
            if (vhi) {
                float2 v;
                v.x = (col < DD)     ? acc[j][2] + bx : 0.f;
                v.y = (col + 1 < DD) ? acc[j][3] + by : 0.f;
                *reinterpret_cast<float2*>(C + (size_t)rhi * NS + col) = v;
            }
        }
    }
}

// ---------------- edge scatter: agg[dst] += hW[src], vectorized red.v4 ----------------
__global__ void scatter_kernel(const int* __restrict__ src, const int* __restrict__ dst) {
    const int warp_id = (blockIdx.x * blockDim.x + threadIdx.x) >> 5;
    const int lane = threadIdx.x & 31;
    if (warp_id >= N_EDGES) return;
    const int s = __ldg(&src[warp_id]);
    const int d = __ldg(&dst[warp_id]);
    const float4* srow = reinterpret_cast<const float4*>(g_hW + (size_t)s * NS);
    float4* drow = reinterpret_cast<float4*>(g_agg + (size_t)d * NS);
    float4 v = __ldg(&srow[lane]);
    red_add_v4(drow + lane, v);
    if (lane < 5) {
        float4 v2 = __ldg(&srow[32 + lane]);
        red_add_v4(drow + 32 + lane, v2);
    }
}

// ---------------- finalize 1: agg = (agg*norm_dst + b)*snorm (in place) + BN col sums ----------------
__global__ void finalize1_kernel(const float* __restrict__ snorm,
                                 const float* __restrict__ bs, int layer)
{
    const int f = threadIdx.x;   // blockDim = 160
    const bool active = (f < DD);
    const float b = active ? __ldg(&bs[layer * DD + f]) : 0.f;
    const int per = (N_NODES + gridDim.x - 1) / gridDim.x;
    const int s = blockIdx.x * per;
    const int e = min(s + per, N_NODES);
    float sum = 0.f, sumsq = 0.f;
#pragma unroll 4
    for (int node = s; node < e; node++) {
        float nd = __ldg(&g_norm_dst[node]);
        float sn = __ldg(&snorm[node]);
        if (active) {
            size_t idx = (size_t)node * NS + f;
            float v = (g_agg[idx] * nd + b) * sn;
            g_agg[idx] = v;
            sum += v;
            sumsq += v * v;
        }
    }
    if (active) {
        atomicAdd(&g_bnsum[f], sum);
        atomicAdd(&g_bnsum[NS + f], sumsq);
    }
}

// ---------------- BN stats (+ self-zero bnsum for next layer) ----------------
__global__ void bn_stats_kernel() {
    const int f = threadIdx.x;   // blockDim = 160
    if (f < DD) {
        const float invN = 1.0f / (float)N_NODES;
        float mean = g_bnsum[f] * invN;
        float var = g_bnsum[NS + f] * invN - mean * mean;
        var = fmaxf(var, 0.f);
        g_mean[f] = mean;
        g_rstd[f] = rsqrtf(var + BN_EPS);
    }
    if (f < NS) { g_bnsum[f] = 0.f; g_bnsum[NS + f] = 0.f; }
}

// ---------------- finalize 2: h += relu(BN(agg)); per-graph hg run-length accumulation ----
__global__ void finalize2_kernel(const float* __restrict__ gammas,
                                 const float* __restrict__ betas,
                                 const int* __restrict__ graph_ids, int layer)
{
    const int f = threadIdx.x;   // blockDim = 160
    const bool active = (f < DD);
    float mean = 0.f, rstd = 0.f, ga = 0.f, be = 0.f;
    if (active) {
        mean = g_mean[f];
        rstd = g_rstd[f];
        ga = __ldg(&gammas[layer * DD + f]);
        be = __ldg(&betas[layer * DD + f]);
    }
    const int per = (N_NODES + gridDim.x - 1) / gridDim.x;
    const int s = blockIdx.x * per;
    const int e = min(s + per, N_NODES);
    int cur = -1;
    float acc = 0.f;
    for (int node = s; node < e; node++) {
        int g = __ldg(&graph_ids[node]);
        if (g != cur) {
            if (cur >= 0 && active) atomicAdd(&g_hg[cur * DD + f], acc);
            cur = g;
            acc = 0.f;
        }
        if (active) {
            size_t idx = (size_t)node * NS + f;
            float bn = (g_agg[idx] - mean) * rstd * ga + be;
            float hnew = g_h[idx] + fmaxf(bn, 0.f);
            g_h[idx] = hnew;
            acc += hnew;
        }
    }
    if (cur >= 0 && active) atomicAdd(&g_hg[cur * DD + f], acc);
}

// ---------------- MLP readout: 146 -> 73 -> 36 -> 10, one block per graph ----------------
__global__ void readout_kernel(const float* __restrict__ W_r0, const float* __restrict__ b_r0,
                               const float* __restrict__ W_r1, const float* __restrict__ b_r1,
                               const float* __restrict__ W_r2, const float* __restrict__ b_r2,
                               float* __restrict__ out)
{
    __shared__ float sh[DD + 73 + 36];
    const int g = blockIdx.x;
    const int t = threadIdx.x;
    const float inv = 1.0f / fmaxf(g_counts[g], 1.0f);
    for (int k = t; k < DD; k += blockDim.x) sh[k] = g_hg[g * DD + k] * inv;
    __syncthreads();
    if (t < 73) {
        float a = b_r0[t];
        for (int k = 0; k < DD; k++) a += sh[k] * W_r0[k * 73 + t];
        sh[DD + t] = fmaxf(a, 0.f);
    }
    __syncthreads();
    if (t < 36) {
        float a = b_r1[t];
        for (int k = 0; k < 73; k++) a += sh[DD + k] * W_r1[k * 36 + t];
        sh[DD + 73 + t] = fmaxf(a, 0.f);
    }
    __syncthreads();
    if (t < 10) {
        float a = b_r2[t];
        for (int k = 0; k < 36; k++) a += sh[DD + 73 + k] * W_r2[k * 10 + t];
        out[g * 10 + t] = a;
    }
}

// ---------------- launch ----------------
extern "C" void kernel_launch(void* const* d_in, const int* in_sizes, int n_in,
                              void* d_out, int out_size)
{
    const float* nodes_feat = (const float*)d_in[0];
    const float* snorm      = (const float*)d_in[1];
    const float* W_emb      = (const float*)d_in[2];
    const float* b_emb      = (const float*)d_in[3];
    const float* Ws         = (const float*)d_in[4];
    const float* bs         = (const float*)d_in[5];
    const float* gammas     = (const float*)d_in[6];
    const float* betas      = (const float*)d_in[7];
    const float* W_r0       = (const float*)d_in[8];
    const float* b_r0       = (const float*)d_in[9];
    const float* W_r1       = (const float*)d_in[10];
    const float* b_r1       = (const float*)d_in[11];
    const float* W_r2       = (const float*)d_in[12];
    const float* b_r2       = (const float*)d_in[13];
    const int*   src        = (const int*)d_in[14];
    const int*   dst        = (const int*)d_in[15];
    const int*   gid        = (const int*)d_in[16];
    float* out = (float*)d_out;

    cudaFuncSetAttribute(mma_gemm_kernel, cudaFuncAttributeMaxDynamicSharedMemorySize,
                         MMA_SMEM_BYTES);

    dim3 gemm_grid((N_NODES + TCM - 1) / TCM, 2);                      // 391 x 2
    const int scatter_blocks = (N_EDGES * 32) / 256;                    // 62500

    zero_init_kernel<<<256, 256>>>();
    deg_kernel<<<(N_EDGES + 255) / 256, 256>>>(src, dst);
    deg_finalize_kernel<<<(N_NODES + 255) / 256, 256>>>(gid);

    // embedding: h = nodes_feat @ W_emb + b_emb
    mma_gemm_kernel<<<gemm_grid, 256, MMA_SMEM_BYTES>>>(nodes_feat, 0, W_emb, b_emb, 0, 0);

    for (int l = 0; l < 4; l++) {
        // hW = (h * norm_src) @ W_l
        mma_gemm_kernel<<<gemm_grid, 256, MMA_SMEM_BYTES>>>(nullptr, 1, Ws + l * DD * DD,
                                                            nullptr, 1, 1);
        zero_agg_kernel<<<1024, 256>>>();
        scatter_kernel<<<scatter_blocks, 256>>>(src, dst);
        finalize1_kernel<<<512, 160>>>(snorm, bs, l);
        bn_stats_kernel<<<1, 160>>>();
        finalize2_kernel<<<1024, 160>>>(gammas, betas, gid, l);
    }

    readout_kernel<<<N_GRAPHS, 128>>>(W_r0, b_r0, W_r1, b_r1, W_r2, b_r2, out);
}

// round 15
// speedup vs baseline: 2.0333x; 1.0650x over previous
#include <cuda_runtime.h>
#include <cuda_bf16.h>
#include <cstdint>

#define N_NODES 50000
#define N_EDGES 500000
#define N_GRAPHS 100
#define DD 146
#define NS 148          // padded row stride (float), 592B = 37 x float4
#define BN_EPS 1e-5f

// ---------------- scratch (static device globals; no allocation) ----------------
__device__ __align__(16) float g_h   [N_NODES * NS];
__device__ __align__(16) float g_hW  [N_NODES * NS];
__device__ __align__(16) float g_agg [N_NODES * NS];
__device__ float g_norm_src[N_NODES];
__device__ float g_norm_dst[N_NODES];
__device__ float g_counts[N_GRAPHS];
__device__ __align__(16) float g_hg[N_GRAPHS * DD];
__device__ float g_bnsum[2 * NS];   // [0:NS) col sums, [NS:2NS) col sumsq
__device__ float g_mean[NS];
__device__ float g_rstd[NS];

// ---------------- helpers ----------------
__device__ __forceinline__ void red_add_v4(float4* p, float4 v) {
    asm volatile("red.global.add.v4.f32 [%0], {%1,%2,%3,%4};"
                 :: "l"(p), "f"(v.x), "f"(v.y), "f"(v.z), "f"(v.w) : "memory");
}
__device__ __forceinline__ uint32_t f2tf32(float x) {
    uint32_t r;
    asm("cvt.rna.tf32.f32 %0, %1;" : "=r"(r) : "f"(x));
    return r;
}
// m16n8k8 tf32 MMA (legacy HMMA path, valid on target sm_100)
__device__ __forceinline__ void mma8(float* c, const uint32_t* a, uint32_t b0, uint32_t b1) {
    asm volatile(
        "mma.sync.aligned.m16n8k8.row.col.f32.tf32.tf32.f32 "
        "{%0,%1,%2,%3}, {%4,%5,%6,%7}, {%8,%9}, {%0,%1,%2,%3};"
        : "+f"(c[0]), "+f"(c[1]), "+f"(c[2]), "+f"(c[3])
        : "r"(a[0]), "r"(a[1]), "r"(a[2]), "r"(a[3]), "r"(b0), "r"(b1));
}

// ---------------- init ----------------
__global__ void zero_init_kernel() {
    int idx = blockIdx.x * blockDim.x + threadIdx.x;
    int stride = gridDim.x * blockDim.x;
    for (int i = idx; i < N_NODES; i += stride) { g_norm_src[i] = 0.f; g_norm_dst[i] = 0.f; }
    for (int i = idx; i < N_GRAPHS * DD; i += stride) g_hg[i] = 0.f;
    for (int i = idx; i < N_GRAPHS; i += stride) g_counts[i] = 0.f;
    for (int i = idx; i < 2 * NS; i += stride) g_bnsum[i] = 0.f;
}

// zero agg right before each scatter (L2 prefetch+dirty; R9 lesson — keep placement)
__global__ void zero_agg_kernel() {
    int idx = blockIdx.x * blockDim.x + threadIdx.x;
    int stride = gridDim.x * blockDim.x;
    const float4 z4 = make_float4(0.f, 0.f, 0.f, 0.f);
    const int n4 = N_NODES * NS / 4;
    float4* agg4 = reinterpret_cast<float4*>(g_agg);
    for (int i = idx; i < n4; i += stride) agg4[i] = z4;
}

// ---------------- degree norms + graph counts ----------------
__global__ void deg_kernel(const int* __restrict__ src, const int* __restrict__ dst) {
    int idx = blockIdx.x * blockDim.x + threadIdx.x;
    int stride = gridDim.x * blockDim.x;
    for (int e = idx; e < N_EDGES; e += stride) {
        atomicAdd(&g_norm_src[src[e]], 1.0f);
        atomicAdd(&g_norm_dst[dst[e]], 1.0f);
    }
}

__global__ void deg_finalize_kernel(const int* __restrict__ graph_ids) {
    int idx = blockIdx.x * blockDim.x + threadIdx.x;
    int stride = gridDim.x * blockDim.x;
    for (int i = idx; i < N_NODES; i += stride) {
        g_norm_src[i] = rsqrtf(fmaxf(g_norm_src[i], 1.0f));
        g_norm_dst[i] = rsqrtf(fmaxf(g_norm_dst[i], 1.0f));
        atomicAdd(&g_counts[graph_ids[i]], 1.0f);
    }
}

// ---------------- mma.sync tf32 GEMM (3-pass split = fp32 accuracy) ----------------
// C[M,NS] = diag(scale?) * A[M,146] @ W[146,146] (+bias)
// R15: TCN 80->40 (5 n8-tiles, grid y=4), smem 48.6KB + regs<=85
// -> 3 blocks/SM (R14: 2 blocks, occ 22.8%, tensor 34.2%).
// D = Ah*Bh + Ah*Bl + Al*Bh  (|Al*Bl| ~ 2^-22, dropped)
#define TCM 128
#define TCN 40     // N cols per block
#define NT 5       // n8 tiles per block
#define NYB 4      // grid.y
#define KPAD 152
#define WST 40     // smem row stride: banks tg*40%32={0,8,16,24} + gid -> 32 distinct
#define W_SMEM_FLOATS (KPAD * WST)
#define MMA_SMEM_BYTES (2 * W_SMEM_FLOATS * 4)   // 48,640 B

__global__ void __launch_bounds__(256, 3)
mma_gemm_kernel(const float* __restrict__ Aext, int use_gh,
                const float* __restrict__ W, const float* __restrict__ bias,
                int use_scale, int out_hw)
{
    extern __shared__ float smem[];
    float* Whi = smem;
    float* Wlo = smem + W_SMEM_FLOATS;
    const float* A = use_gh ? g_h : Aext;
    const int lda = use_gh ? NS : DD;
    float* C = out_hw ? g_hW : g_h;
    const int tid = threadIdx.x;
    const int n0 = blockIdx.y * TCN;

    // stage W column slice [all k][n0..n0+TCN): hi = tf32(w), lo = tf32(w - hi)
    for (int i = tid; i < KPAD * TCN; i += 256) {
        int k = i / TCN, n = i - (i / TCN) * TCN;
        int gn = n0 + n;
        float w = (k < DD && gn < DD) ? __ldg(&W[k * DD + gn]) : 0.f;
        float whi = __uint_as_float(f2tf32(w));
        float wlo = __uint_as_float(f2tf32(w - whi));
        Whi[k * WST + n] = whi;
        Wlo[k * WST + n] = wlo;
    }
    __syncthreads();

    const int warp = tid >> 5;
    const int lane = tid & 31;
    const int tg = lane & 3;          // thread-in-group (k / col-pair selector)
    const int gid = lane >> 2;        // group id (row / n selector)
    const int rlo = blockIdx.x * TCM + warp * 16 + gid;
    const int rhi = rlo + 8;
    const bool vlo = rlo < N_NODES, vhi = rhi < N_NODES;
    const float slo = (use_scale && vlo) ? g_norm_src[rlo] : 1.f;
    const float shi = (use_scale && vhi) ? g_norm_src[rhi] : 1.f;
    const float* Aplo = A + (size_t)rlo * lda;
    const float* Aphi = A + (size_t)rhi * lda;

    float acc[NT][4];
#pragma unroll
    for (int j = 0; j < NT; j++) {
        acc[j][0] = 0.f; acc[j][1] = 0.f; acc[j][2] = 0.f; acc[j][3] = 0.f;
    }

    // prefetch k-step 0 (cols tg, tg+4 < 146 always)
    float ar0 = vlo ? Aplo[tg] * slo : 0.f;
    float ar1 = vhi ? Aphi[tg] * shi : 0.f;
    float ar2 = vlo ? Aplo[tg + 4] * slo : 0.f;
    float ar3 = vhi ? Aphi[tg + 4] * shi : 0.f;

#pragma unroll 1
    for (int s = 0; s < 19; s++) {
        float a0 = ar0, a1 = ar1, a2 = ar2, a3 = ar3;
        if (s < 18) {
            int c0 = 8 * (s + 1) + tg, c1 = c0 + 4;
            bool g0 = c0 < DD, g1 = c1 < DD;
            ar0 = (vlo && g0) ? Aplo[c0] * slo : 0.f;
            ar1 = (vhi && g0) ? Aphi[c0] * shi : 0.f;
            ar2 = (vlo && g1) ? Aplo[c1] * slo : 0.f;
            ar3 = (vhi && g1) ? Aphi[c1] * shi : 0.f;
        }
        uint32_t ah[4], al[4];
        ah[0] = f2tf32(a0); al[0] = f2tf32(a0 - __uint_as_float(ah[0]));
        ah[1] = f2tf32(a1); al[1] = f2tf32(a1 - __uint_as_float(ah[1]));
        ah[2] = f2tf32(a2); al[2] = f2tf32(a2 - __uint_as_float(ah[2]));
        ah[3] = f2tf32(a3); al[3] = f2tf32(a3 - __uint_as_float(ah[3]));

        const float* wh = Whi + 8 * s * WST;
        const float* wl = Wlo + 8 * s * WST;
#pragma unroll
        for (int j = 0; j < NT; j++) {
            int nn = j * 8 + gid;   // local col within block slice
            uint32_t bh0 = __float_as_uint(wh[tg * WST + nn]);
            uint32_t bh1 = __float_as_uint(wh[(tg + 4) * WST + nn]);
            uint32_t bl0 = __float_as_uint(wl[tg * WST + nn]);
            uint32_t bl1 = __float_as_uint(wl[(tg + 4) * WST + nn]);
            mma8(acc[j], ah, bh0, bh1);
            mma8(acc[j], ah, bl0, bl1);
            mma8(acc[j], al, bh0, bh1);
        }
    }

    // epilogue: c0/c1 -> row rlo cols (n0+8j+2tg, +1); c2/c3 -> row rhi
#pragma unroll
    for (int j = 0; j < NT; j++) {
        int col = n0 + j * 8 + 2 * tg;
        if (col < NS) {   // col even -> col+1 < NS whenever col < NS
            float bx = 0.f, by = 0.f;
            if (bias) {
                if (col < DD)     bx = __ldg(&bias[col]);
                if (col + 1 < DD) by = __ldg(&bias[col + 1]);
            }
            if (vlo) {
                float2 v;
                v.x = (col < DD)     ? acc[j][0] + bx : 0.f;
                v.y = (col + 1 < DD) ? acc[j][1] + by : 0.f;
                *reinterpret_cast<float2*>(C + (size_t)rlo * NS + col) = v;
            }
            if (vhi) {
                float2 v;
                v.x = (col < DD)     ? acc[j][2] + bx : 0.f;
                v.y = (col + 1 < DD) ? acc[j][3] + by : 0.f;
                *reinterpret_cast<float2*>(C + (size_t)rhi * NS + col) = v;
            }
        }
    }
}

// ---------------- edge scatter: agg[dst] += hW[src], vectorized red.v4 ----------------
__global__ void scatter_kernel(const int* __restrict__ src, const int* __restrict__ dst) {
    const int warp_id = (blockIdx.x * blockDim.x + threadIdx.x) >> 5;
    const int lane = threadIdx.x & 31;
    if (warp_id >= N_EDGES) return;
    const int s = __ldg(&src[warp_id]);
    const int d = __ldg(&dst[warp_id]);
    const float4* srow = reinterpret_cast<const float4*>(g_hW + (size_t)s * NS);
    float4* drow = reinterpret_cast<float4*>(g_agg + (size_t)d * NS);
    float4 v = __ldg(&srow[lane]);
    red_add_v4(drow + lane, v);
    if (lane < 5) {
        float4 v2 = __ldg(&srow[32 + lane]);
        red_add_v4(drow + 32 + lane, v2);
    }
}

// ---------------- finalize 1 (R15: stats only, no write-back; saves 30MB/layer) -----
// v = (agg*norm_dst + b)*snorm computed on the fly; column sums/sumsq -> g_bnsum.
__global__ void finalize1_kernel(const float* __restrict__ snorm,
                                 const float* __restrict__ bs, int layer)
{
    const int f = threadIdx.x;   // blockDim = 160
    const bool active = (f < DD);
    const float b = active ? __ldg(&bs[layer * DD + f]) : 0.f;
    const int per = (N_NODES + gridDim.x - 1) / gridDim.x;
    const int s = blockIdx.x * per;
    const int e = min(s + per, N_NODES);
    float sum = 0.f, sumsq = 0.f;
#pragma unroll 4
    for (int node = s; node < e; node++) {
        float nd = __ldg(&g_norm_dst[node]);
        float sn = __ldg(&snorm[node]);
        if (active) {
            float v = (g_agg[(size_t)node * NS + f] * nd + b) * sn;
            sum += v;
            sumsq += v * v;
        }
    }
    if (active) {
        atomicAdd(&g_bnsum[f], sum);
        atomicAdd(&g_bnsum[NS + f], sumsq);
    }
}

// ---------------- BN stats (+ self-zero bnsum for next layer) ----------------
__global__ void bn_stats_kernel() {
    const int f = threadIdx.x;   // blockDim = 160
    if (f < DD) {
        const float invN = 1.0f / (float)N_NODES;
        float mean = g_bnsum[f] * invN;
        float var = g_bnsum[NS + f] * invN - mean * mean;
        var = fmaxf(var, 0.f);
        g_mean[f] = mean;
        g_rstd[f] = rsqrtf(var + BN_EPS);
    }
    if (f < NS) { g_bnsum[f] = 0.f; g_bnsum[NS + f] = 0.f; }
}

// ---------------- finalize 2: recompute v from raw agg; h += relu(BN(v));
// per-graph hg run-length accumulation. agg NOT zeroed here (zero_agg keeps
// L2 residency right before the next scatter — R9/R10 lesson).
__global__ void finalize2_kernel(const float* __restrict__ gammas,
                                 const float* __restrict__ betas,
                                 const float* __restrict__ snorm,
                                 const float* __restrict__ bs,
                                 const int* __restrict__ graph_ids, int layer)
{
    const int f = threadIdx.x;   // blockDim = 160
    const bool active = (f < DD);
    float mean = 0.f, rstd = 0.f, ga = 0.f, be = 0.f, b = 0.f;
    if (active) {
        mean = g_mean[f];
        rstd = g_rstd[f];
        ga = __ldg(&gammas[layer * DD + f]);
        be = __ldg(&betas[layer * DD + f]);
        b  = __ldg(&bs[layer * DD + f]);
    }
    const int per = (N_NODES + gridDim.x - 1) / gridDim.x;
    const int s = blockIdx.x * per;
    const int e = min(s + per, N_NODES);
    int cur = -1;
    float acc = 0.f;
    for (int node = s; node < e; node++) {
        int g = __ldg(&graph_ids[node]);
        if (g != cur) {
            if (cur >= 0 && active) atomicAdd(&g_hg[cur * DD + f], acc);
            cur = g;
            acc = 0.f;
        }
        if (active) {
            size_t idx = (size_t)node * NS + f;
            float nd = __ldg(&g_norm_dst[node]);
            float sn = __ldg(&snorm[node]);
            float v = (g_agg[idx] * nd + b) * sn;
            float bn = (v - mean) * rstd * ga + be;
            float hnew = g_h[idx] + fmaxf(bn, 0.f);
            g_h[idx] = hnew;
            acc += hnew;
        }
    }
    if (cur >= 0 && active) atomicAdd(&g_hg[cur * DD + f], acc);
}

// ---------------- MLP readout: 146 -> 73 -> 36 -> 10, one block per graph ----------------
__global__ void readout_kernel(const float* __restrict__ W_r0, const float* __restrict__ b_r0,
                               const float* __restrict__ W_r1, const float* __restrict__ b_r1,
                               const float* __restrict__ W_r2, const float* __restrict__ b_r2,
                               float* __restrict__ out)
{
    __shared__ float sh[DD + 73 + 36];
    const int g = blockIdx.x;
    const int t = threadIdx.x;
    const float inv = 1.0f / fmaxf(g_counts[g], 1.0f);
    for (int k = t; k < DD; k += blockDim.x) sh[k] = g_hg[g * DD + k] * inv;
    __syncthreads();
    if (t < 73) {
        float a = b_r0[t];
        for (int k = 0; k < DD; k++) a += sh[k] * W_r0[k * 73 + t];
        sh[DD + t] = fmaxf(a, 0.f);
    }
    __syncthreads();
    if (t < 36) {
        float a = b_r1[t];
        for (int k = 0; k < 73; k++) a += sh[DD + k] * W_r1[k * 36 + t];
        sh[DD + 73 + t] = fmaxf(a, 0.f);
    }
    __syncthreads();
    if (t < 10) {
        float a = b_r2[t];
        for (int k = 0; k < 36; k++) a += sh[DD + 73 + k] * W_r2[k * 10 + t];
        out[g * 10 + t] = a;
    }
}

// ---------------- launch ----------------
extern "C" void kernel_launch(void* const* d_in, const int* in_sizes, int n_in,
                              void* d_out, int out_size)
{
    const float* nodes_feat = (const float*)d_in[0];
    const float* snorm      = (const float*)d_in[1];
    const float* W_emb      = (const float*)d_in[2];
    const float* b_emb      = (const float*)d_in[3];
    const float* Ws         = (const float*)d_in[4];
    const float* bs         = (const float*)d_in[5];
    const float* gammas     = (const float*)d_in[6];
    const float* betas      = (const float*)d_in[7];
    const float* W_r0       = (const float*)d_in[8];
    const float* b_r0       = (const float*)d_in[9];
    const float* W_r1       = (const float*)d_in[10];
    const float* b_r1       = (const float*)d_in[11];
    const float* W_r2       = (const float*)d_in[12];
    const float* b_r2       = (const float*)d_in[13];
    const int*   src        = (const int*)d_in[14];
    const int*   dst        = (const int*)d_in[15];
    const int*   gid        = (const int*)d_in[16];
    float* out = (float*)d_out;

    cudaFuncSetAttribute(mma_gemm_kernel, cudaFuncAttributeMaxDynamicSharedMemorySize,
                         MMA_SMEM_BYTES);

    dim3 gemm_grid((N_NODES + TCM - 1) / TCM, NYB);                    // 391 x 4
    const int scatter_blocks = (N_EDGES * 32) / 256;                    // 62500

    zero_init_kernel<<<256, 256>>>();
    deg_kernel<<<(N_EDGES + 255) / 256, 256>>>(src, dst);
    deg_finalize_kernel<<<(N_NODES + 255) / 256, 256>>>(gid);

    // embedding: h = nodes_feat @ W_emb + b_emb
    mma_gemm_kernel<<<gemm_grid, 256, MMA_SMEM_BYTES>>>(nodes_feat, 0, W_emb, b_emb, 0, 0);

    for (int l = 0; l < 4; l++) {
        // hW = (h * norm_src) @ W_l
        mma_gemm_kernel<<<gemm_grid, 256, MMA_SMEM_BYTES>>>(nullptr, 1, Ws + l * DD * DD,
                                                            nullptr, 1, 1);
        zero_agg_kernel<<<1024, 256>>>();
        scatter_kernel<<<scatter_blocks, 256>>>(src, dst);
        finalize1_kernel<<<512, 160>>>(snorm, bs, l);
        bn_stats_kernel<<<1, 160>>>();
        finalize2_kernel<<<1024, 160>>>(gammas, betas, snorm, bs, gid, l);
    }

    readout_kernel<<<N_GRAPHS, 128>>>(W_r0, b_r0, W_r1, b_r1, W_r2, b_r2, out);
}